// round 14
// baseline (speedup 1.0000x reference)
#include <cuda_runtime.h>
#include <math.h>
#include <float.h>

#define BSZ   64
#define SEQ   128
#define INP   256
#define HH    512
#define NN    4096
#define MM    128
#define RHEAD 4
#define NOUT  64
#define GAMMA 0.95f
#define KTOT  769
#define NBLK  148
#define TPB   512
#define NROWS (BSZ*NN)
#define RPW   111

typedef unsigned long long ull;

__device__ __align__(16) float g_mem[(size_t)BSZ*NN*MM];
__device__ __align__(16) float g_rwbuf[2][BSZ*RHEAD*NN];
__device__ __align__(16) float g_uw[BSZ*NN];
__device__ float g_wws[BSZ*NN];
__device__ __align__(16) float g_dots[BSZ*RHEAD*NN];
__device__ float g_query[BSZ*HH];
__device__ float g_hid[2][BSZ*HH];
__device__ float g_cell[BSZ*HH];
__device__ float g_outputs[(size_t)BSZ*SEQ*1024];
__device__ float g_alpha_s[BSZ*RHEAD];
__device__ int   g_idx[BSZ*RHEAD];
__device__ float g_q2a[2];
__device__ float g_m2a[2];
__device__ int   g_gcnt[2];
__device__ __align__(128) unsigned g_bar_cnt = 0;
__device__ __align__(128) unsigned g_bar_gen = 0;

// ---------------- packed f32x2 helpers (per-lane IEEE ops, bit-identical) -----
__device__ __forceinline__ ull pk2(float a, float b) {
    ull r; asm("mov.b64 %0, {%1,%2};" : "=l"(r) : "f"(a), "f"(b)); return r;
}
__device__ __forceinline__ void upk2(ull p, float& a, float& b) {
    asm("mov.b64 {%0,%1}, %2;" : "=f"(a), "=f"(b) : "l"(p));
}
__device__ __forceinline__ ull fma2_(ull a, ull b, ull c) {
    ull d; asm("fma.rn.f32x2 %0, %1, %2, %3;" : "=l"(d) : "l"(a), "l"(b), "l"(c)); return d;
}
__device__ __forceinline__ ull mul2_(ull a, ull b) {
    ull d; asm("mul.rn.f32x2 %0, %1, %2;" : "=l"(d) : "l"(a), "l"(b)); return d;
}
__device__ __forceinline__ ull add2_(ull a, ull b) {
    ull d; asm("add.rn.f32x2 %0, %1, %2;" : "=l"(d) : "l"(a), "l"(b)); return d;
}

struct UCtx {
    float4 ql0, ql1, ql2, ql3;
    ull q0xy, q0zw, q1xy, q1zw, q2xy, q2zw, q3xy, q3zw;
    float as0, as1, as2, as3, wc0, wc1, wc2, wc3;
    int ix0, ix1, ix2, ix3;
};
struct UAcc {
    ull rv0xy, rv0zw, rv1xy, rv1zw, rv2xy, rv2zw, rv3xy, rv3zw;
    ull m2a, m2b;
};

__device__ __forceinline__ void grid_sync() {
    __syncthreads();
    if (threadIdx.x == 0) {
        unsigned gen;
        asm volatile("ld.acquire.gpu.u32 %0, [%1];" : "=r"(gen) : "l"(&g_bar_gen));
        unsigned prev;
        asm volatile("atom.acq_rel.gpu.global.add.u32 %0, [%1], %2;"
                     : "=r"(prev) : "l"(&g_bar_cnt), "r"(1u) : "memory");
        if (prev == (unsigned)gridDim.x - 1u) {
            asm volatile("st.relaxed.gpu.u32 [%0], %1;" :: "l"(&g_bar_cnt), "r"(0u) : "memory");
            asm volatile("red.release.gpu.global.add.u32 [%0], %1;" :: "l"(&g_bar_gen), "r"(1u) : "memory");
        } else {
            unsigned cur;
            do {
                asm volatile("ld.acquire.gpu.u32 %0, [%1];" : "=r"(cur) : "l"(&g_bar_gen));
            } while (cur == gen);
        }
    }
    __syncthreads();
}

// ---------------- init: vectorized copies into scratch --------------------------
__global__ void k_init(const float* __restrict__ mem_in,
                       const float* __restrict__ rw_in,
                       const float* __restrict__ uw_in,
                       const float* __restrict__ alpha) {
    long tid = (long)blockIdx.x * blockDim.x + threadIdx.x;
    long stride = (long)gridDim.x * blockDim.x;
    const long MEM4 = (long)BSZ*NN*MM/4;
    const float4* src4 = (const float4*)mem_in;
    float4* dst4 = (float4*)g_mem;
    for (long i = tid; i < MEM4; i += stride) dst4[i] = src4[i];
    float4* rwi = (float4*)g_rwbuf[0];
    for (long i = tid; i < (long)BSZ*NN; i += stride) {
        long b = i >> 12, n = i & 4095;
        const float* rp = rw_in + ((b << 2) << 12) + n;
        float4 v;
        v.x = rp[0];
        v.y = rp[NN];
        v.z = rp[2 * NN];
        v.w = rp[3 * NN];
        rwi[i] = v;
    }
    const long UW4 = (long)BSZ*NN/4;
    const float4* us4 = (const float4*)uw_in;
    float4* ud4 = (float4*)g_uw;
    for (long i = tid; i < UW4; i += stride) ud4[i] = us4[i];
    if (tid < BSZ*RHEAD) g_alpha_s[tid] = 1.0f / (1.0f + expf(-alpha[tid]));
}

__device__ void gemm_gates(const float* __restrict__ x, const float* __restrict__ y,
                           const float* __restrict__ Wl, const float* __restrict__ bl,
                           int t, float* sbuf, int tid, int jblk) {
    float* As = sbuf;
    float* Bs = sbuf + 2112;
    float* Ps = sbuf + 3136;
    const int j0 = jblk * 8;
    const int row = tid >> 3;
    const int cg  = tid & 7;
    const float* hprev = g_hid[(t & 1) ^ 1];

    float acc[4] = {0.f, 0.f, 0.f, 0.f};

    for (int kb = 0; kb < KTOT; kb += 32) {
        #pragma unroll
        for (int i = 0; i < 4; i++) {
            int e = tid + i * 512;
            int r = e >> 5, k = e & 31;
            int kg = kb + k;
            float v = 0.f;
            if (kg < INP) v = x[(r * SEQ + t) * INP + kg];
            else if (kg == INP) { if (t > 0) v = y[r * SEQ + t - 1]; }
            else if (kg < KTOT) { if (t > 0) v = hprev[r * HH + kg - INP - 1]; }
            As[r * 33 + k] = v;
        }
        #pragma unroll
        for (int i = 0; i < 2; i++) {
            int e = tid + i * 512;
            int k = e >> 5, c = e & 31;
            int kg = kb + k;
            float v = 0.f;
            if (kg < KTOT) {
                int g = c >> 3, jj = c & 7;
                v = Wl[kg * (4 * HH) + g * HH + j0 + jj];
            }
            Bs[k * 32 + c] = v;
        }
        __syncthreads();
        #pragma unroll
        for (int k = 0; k < 32; k++) {
            float a = As[row * 33 + k];
            float4 bv = *(const float4*)&Bs[k * 32 + cg * 4];
            acc[0] += a * bv.x; acc[1] += a * bv.y; acc[2] += a * bv.z; acc[3] += a * bv.w;
        }
        __syncthreads();
    }
    #pragma unroll
    for (int i = 0; i < 4; i++) Ps[row * 32 + cg * 4 + i] = acc[i];
    __syncthreads();

    float* hcur = g_hid[t & 1];
    {
        int b = tid >> 3, jj = tid & 7;
        int j = j0 + jj;
        float pf = Ps[b * 32 +  0 + jj] + bl[0 * HH + j];
        float pi = Ps[b * 32 +  8 + jj] + bl[1 * HH + j];
        float po = Ps[b * 32 + 16 + jj] + bl[2 * HH + j];
        float pu = Ps[b * 32 + 24 + jj] + bl[3 * HH + j];
        float f  = 1.f / (1.f + expf(-pf));
        float ig = 1.f / (1.f + expf(-pi));
        float o  = 1.f / (1.f + expf(-po));
        float uu = tanhf(pu);
        float cprev = (t > 0) ? g_cell[b * HH + j] : 0.f;
        float c = f * cprev + ig * uu;
        float h = o * tanhf(c);
        g_cell[b * HH + j] = c;
        hcur[b * HH + j] = h;
        g_outputs[((size_t)b * SEQ + t) * 1024 + j] = h;
    }
}

__device__ void query_phase(int b, int t, const float* __restrict__ Wm,
                            const float* __restrict__ bm, float* sbuf, int tid) {
    const float* h = g_hid[t & 1] + b * HH;
    sbuf[tid] = h[tid];
    __syncthreads();
    float a0 = 0.f, a1 = 0.f, a2 = 0.f, a3 = 0.f;
    #pragma unroll 4
    for (int k = 0; k < HH; k += 4) {
        a0 += sbuf[k]     * Wm[(k)     * HH + tid];
        a1 += sbuf[k + 1] * Wm[(k + 1) * HH + tid];
        a2 += sbuf[k + 2] * Wm[(k + 2) * HH + tid];
        a3 += sbuf[k + 3] * Wm[(k + 3) * HH + tid];
    }
    float qv = a0 + a1 + a2 + a3 + bm[tid];
    g_query[b * HH + tid] = qv;
    float* red = sbuf + 1024;
    red[tid] = qv * qv;
    __syncthreads();
    for (int s = 256; s > 0; s >>= 1) {
        if (tid < s) red[tid] += red[tid + s];
        __syncthreads();
    }
    if (tid == 0) atomicAdd(&g_q2a[t & 1], red[0]);
}

__device__ void idx_phase(int b, float* sbuf, int tid) {
    float v[8]; int nn[8];
    #pragma unroll
    for (int i = 0; i < 8; i++) { int n = tid + i * 512; v[i] = g_uw[b * NN + n]; nn[i] = n; }
    float* sval = sbuf;
    int*   sidx = (int*)(sbuf + 512);
    for (int sel = 0; sel < 4; sel++) {
        float bv = FLT_MAX; int bn = 0x7fffffff;
        #pragma unroll
        for (int i = 0; i < 8; i++)
            if (v[i] < bv || (v[i] == bv && nn[i] < bn)) { bv = v[i]; bn = nn[i]; }
        sval[tid] = bv; sidx[tid] = bn;
        __syncthreads();
        for (int s = 256; s > 0; s >>= 1) {
            if (tid < s) {
                float ov = sval[tid + s]; int on = sidx[tid + s];
                if (ov < sval[tid] || (ov == sval[tid] && on < sidx[tid])) {
                    sval[tid] = ov; sidx[tid] = on;
                }
            }
            __syncthreads();
        }
        int win = sidx[0];
        if (tid == 0) g_idx[b * 4 + sel] = win;
        __syncthreads();
        #pragma unroll
        for (int i = 0; i < 8; i++) if (nn[i] == win) v[i] = FLT_MAX;
    }
}

// ---------------- per-row fused body ---------------------------------------------
__device__ __forceinline__ void urow(int row, float4 v, float4 a,
                                     const UCtx& C, UAcc& A, int lane) {
    ull vxy = pk2(v.x, v.y), vzw = pk2(v.z, v.w);
    ull t;
    t = pk2(a.x, a.x); A.rv0xy = fma2_(t, vxy, A.rv0xy); A.rv0zw = fma2_(t, vzw, A.rv0zw);
    t = pk2(a.y, a.y); A.rv1xy = fma2_(t, vxy, A.rv1xy); A.rv1zw = fma2_(t, vzw, A.rv1zw);
    t = pk2(a.z, a.z); A.rv2xy = fma2_(t, vxy, A.rv2xy); A.rv2zw = fma2_(t, vzw, A.rv2zw);
    t = pk2(a.w, a.w); A.rv3xy = fma2_(t, vxy, A.rv3xy); A.rv3zw = fma2_(t, vzw, A.rv3zw);

    int n = row & 4095;
    float w0 = __fmul_rn(C.as0, a.x); if (C.ix0 == n) w0 = __fadd_rn(w0, C.wc0);
    float w1 = __fmul_rn(C.as1, a.y); if (C.ix1 == n) w1 = __fadd_rn(w1, C.wc1);
    float w2 = __fmul_rn(C.as2, a.z); if (C.ix2 == n) w2 = __fadd_rn(w2, C.wc2);
    float w3 = __fmul_rn(C.as3, a.w); if (C.ix3 == n) w3 = __fadd_rn(w3, C.wc3);
    ull w0p = pk2(w0, w0), w1p = pk2(w1, w1), w2p = pk2(w2, w2), w3p = pk2(w3, w3);
    ull sxy = fma2_(w3p, C.q3xy, fma2_(w2p, C.q2xy, fma2_(w1p, C.q1xy, mul2_(w0p, C.q0xy))));
    ull szw = fma2_(w3p, C.q3zw, fma2_(w2p, C.q2zw, fma2_(w1p, C.q1zw, mul2_(w0p, C.q0zw))));
    vxy = add2_(vxy, sxy);
    vzw = add2_(vzw, szw);
    upk2(vxy, v.x, v.y);
    upk2(vzw, v.z, v.w);
    __stcs((float4*)(g_mem + ((size_t)row << 7) + (lane << 2)), v);

    float d0 = C.ql0.x*v.x + C.ql0.y*v.y + C.ql0.z*v.z + C.ql0.w*v.w;
    float d1 = C.ql1.x*v.x + C.ql1.y*v.y + C.ql1.z*v.z + C.ql1.w*v.w;
    float d2 = C.ql2.x*v.x + C.ql2.y*v.y + C.ql2.z*v.z + C.ql2.w*v.w;
    float d3 = C.ql3.x*v.x + C.ql3.y*v.y + C.ql3.z*v.z + C.ql3.w*v.w;
    d0 += __shfl_xor_sync(0xffffffffu, d0, 16);
    d1 += __shfl_xor_sync(0xffffffffu, d1, 16);
    d2 += __shfl_xor_sync(0xffffffffu, d2, 16);
    d3 += __shfl_xor_sync(0xffffffffu, d3, 16);
    d0 += __shfl_xor_sync(0xffffffffu, d0, 8);
    d1 += __shfl_xor_sync(0xffffffffu, d1, 8);
    d2 += __shfl_xor_sync(0xffffffffu, d2, 8);
    d3 += __shfl_xor_sync(0xffffffffu, d3, 8);
    int g = lane >> 3;
    float dv = (g == 0) ? d0 : (g == 1) ? d1 : (g == 2) ? d2 : d3;
    dv += __shfl_xor_sync(0xffffffffu, dv, 4);
    dv += __shfl_xor_sync(0xffffffffu, dv, 2);
    dv += __shfl_xor_sync(0xffffffffu, dv, 1);
    if ((lane & 7) == 0) g_dots[((size_t)row << 2) + g] = dv;
    if (lane == 0) g_wws[row] = __fadd_rn(__fadd_rn(__fadd_rn(w0, w1), w2), w3);
    A.m2a = fma2_(vxy, vxy, A.m2a);
    A.m2b = fma2_(vzw, vzw, A.m2b);
}

__device__ void update_phase(const float4* __restrict__ rw4, int bx, int tid,
                             float* sbuf, int t) {
    const int p = t & 1;
    if (bx == 147 && tid == 0) { g_q2a[p ^ 1] = 0.f; g_m2a[p ^ 1] = 0.f; }
    if (bx == 146 && tid == 0) { g_gcnt[p] = 0; }
    int lane = tid & 31;
    int w = bx * 16 + (tid >> 5);
    int r0 = w * RPW;
    int r1 = r0 + RPW; if (r1 > NROWS) r1 = NROWS;
    UAcc A;
    A.m2a = 0ull; A.m2b = 0ull;
    int row = r0;
    while (row < r1) {
        int b = row >> 12;
        int bend = (b + 1) << 12; if (bend > r1) bend = r1;
        UCtx C;
        const float* qb = g_query + b * HH;
        C.ql0 = *(const float4*)(qb + 0 * 128 + lane * 4);
        C.ql1 = *(const float4*)(qb + 1 * 128 + lane * 4);
        C.ql2 = *(const float4*)(qb + 2 * 128 + lane * 4);
        C.ql3 = *(const float4*)(qb + 3 * 128 + lane * 4);
        C.q0xy = pk2(C.ql0.x, C.ql0.y); C.q0zw = pk2(C.ql0.z, C.ql0.w);
        C.q1xy = pk2(C.ql1.x, C.ql1.y); C.q1zw = pk2(C.ql1.z, C.ql1.w);
        C.q2xy = pk2(C.ql2.x, C.ql2.y); C.q2zw = pk2(C.ql2.z, C.ql2.w);
        C.q3xy = pk2(C.ql3.x, C.ql3.y); C.q3zw = pk2(C.ql3.z, C.ql3.w);
        C.as0 = g_alpha_s[b*4+0]; C.as1 = g_alpha_s[b*4+1];
        C.as2 = g_alpha_s[b*4+2]; C.as3 = g_alpha_s[b*4+3];
        C.wc0 = 1.f - C.as0; C.wc1 = 1.f - C.as1; C.wc2 = 1.f - C.as2; C.wc3 = 1.f - C.as3;
        C.ix0 = g_idx[b*4+0]; C.ix1 = g_idx[b*4+1];
        C.ix2 = g_idx[b*4+2]; C.ix3 = g_idx[b*4+3];
        A.rv0xy = 0ull; A.rv0zw = 0ull; A.rv1xy = 0ull; A.rv1zw = 0ull;
        A.rv2xy = 0ull; A.rv2zw = 0ull; A.rv3xy = 0ull; A.rv3zw = 0ull;

        // software-pipelined 4-row groups: next group's mem loads issue BEFORE
        // the current group's stores, so DRAM latency hides under compute.
        if (row + 4 <= bend) {
            float4 v0 = __ldcs((const float4*)(g_mem + ((size_t)(row    ) << 7) + (lane << 2)));
            float4 v1 = __ldcs((const float4*)(g_mem + ((size_t)(row + 1) << 7) + (lane << 2)));
            float4 v2 = __ldcs((const float4*)(g_mem + ((size_t)(row + 2) << 7) + (lane << 2)));
            float4 v3 = __ldcs((const float4*)(g_mem + ((size_t)(row + 3) << 7) + (lane << 2)));
            while (row + 8 <= bend) {
                float4 n0 = __ldcs((const float4*)(g_mem + ((size_t)(row + 4) << 7) + (lane << 2)));
                float4 n1 = __ldcs((const float4*)(g_mem + ((size_t)(row + 5) << 7) + (lane << 2)));
                float4 n2 = __ldcs((const float4*)(g_mem + ((size_t)(row + 6) << 7) + (lane << 2)));
                float4 n3 = __ldcs((const float4*)(g_mem + ((size_t)(row + 7) << 7) + (lane << 2)));
                urow(row,     v0, rw4[row    ], C, A, lane);
                urow(row + 1, v1, rw4[row + 1], C, A, lane);
                urow(row + 2, v2, rw4[row + 2], C, A, lane);
                urow(row + 3, v3, rw4[row + 3], C, A, lane);
                v0 = n0; v1 = n1; v2 = n2; v3 = n3;
                row += 4;
            }
            urow(row,     v0, rw4[row    ], C, A, lane);
            urow(row + 1, v1, rw4[row + 1], C, A, lane);
            urow(row + 2, v2, rw4[row + 2], C, A, lane);
            urow(row + 3, v3, rw4[row + 3], C, A, lane);
            row += 4;
        }
        for (; row < bend; row++) {
            float4 v = __ldcs((const float4*)(g_mem + ((size_t)row << 7) + (lane << 2)));
            urow(row, v, rw4[row], C, A, lane);
        }
        if (t > 0) {
            float4 rv0, rv1, rv2, rv3;
            upk2(A.rv0xy, rv0.x, rv0.y); upk2(A.rv0zw, rv0.z, rv0.w);
            upk2(A.rv1xy, rv1.x, rv1.y); upk2(A.rv1zw, rv1.z, rv1.w);
            upk2(A.rv2xy, rv2.x, rv2.y); upk2(A.rv2zw, rv2.z, rv2.w);
            upk2(A.rv3xy, rv3.x, rv3.y); upk2(A.rv3zw, rv3.z, rv3.w);
            float* dst = g_outputs + ((size_t)b * SEQ + (t - 1)) * 1024 + 512 + lane * 4;
            atomicAdd(dst + 0,       rv0.x); atomicAdd(dst + 1,       rv0.y);
            atomicAdd(dst + 2,       rv0.z); atomicAdd(dst + 3,       rv0.w);
            atomicAdd(dst + 128 + 0, rv1.x); atomicAdd(dst + 128 + 1, rv1.y);
            atomicAdd(dst + 128 + 2, rv1.z); atomicAdd(dst + 128 + 3, rv1.w);
            atomicAdd(dst + 256 + 0, rv2.x); atomicAdd(dst + 256 + 1, rv2.y);
            atomicAdd(dst + 256 + 2, rv2.z); atomicAdd(dst + 256 + 3, rv2.w);
            atomicAdd(dst + 384 + 0, rv3.x); atomicAdd(dst + 384 + 1, rv3.y);
            atomicAdd(dst + 384 + 2, rv3.z); atomicAdd(dst + 384 + 3, rv3.w);
        }
    }
    float m2;
    {
        float ax, ay, bx2, by;
        upk2(A.m2a, ax, ay);
        upk2(A.m2b, bx2, by);
        m2 = (ax + ay) + (bx2 + by);
    }
    #pragma unroll
    for (int o = 16; o > 0; o >>= 1) m2 += __shfl_xor_sync(0xffffffffu, m2, o);
    if (lane == 0) sbuf[tid >> 5] = m2;
    __syncthreads();
    if (tid < 16) {
        float v = sbuf[tid];
        #pragma unroll
        for (int o = 8; o > 0; o >>= 1) v += __shfl_xor_sync(0x0000ffffu, v, o);
        if (tid == 0) atomicAdd(&g_m2a[p], v);
    }
}

__device__ void softmax_uw_phase(float* __restrict__ rwn, int b, int ts,
                                 float* sbuf, int tid) {
    float inv = 1.f / __fmul_rn(sqrtf(g_q2a[ts & 1]), sqrtf(g_m2a[ts & 1]));
    const float4* D = (const float4*)g_dots + (size_t)b * NN;
    float4* rw4 = (float4*)rwn + (size_t)b * NN;
    float4* red = (float4*)sbuf;
    float4 lv[8];
    float4 mx = make_float4(-FLT_MAX, -FLT_MAX, -FLT_MAX, -FLT_MAX);
    #pragma unroll
    for (int i = 0; i < 8; i++) {
        float4 d = D[tid + i * 512];
        lv[i].x = d.x * inv; lv[i].y = d.y * inv; lv[i].z = d.z * inv; lv[i].w = d.w * inv;
        mx.x = fmaxf(mx.x, lv[i].x); mx.y = fmaxf(mx.y, lv[i].y);
        mx.z = fmaxf(mx.z, lv[i].z); mx.w = fmaxf(mx.w, lv[i].w);
    }
    red[tid] = mx; __syncthreads();
    for (int s = 256; s > 0; s >>= 1) {
        if (tid < s) {
            float4 o = red[tid + s];
            red[tid].x = fmaxf(red[tid].x, o.x); red[tid].y = fmaxf(red[tid].y, o.y);
            red[tid].z = fmaxf(red[tid].z, o.z); red[tid].w = fmaxf(red[tid].w, o.w);
        }
        __syncthreads();
    }
    mx = red[0]; __syncthreads();
    float4 sum = make_float4(0.f, 0.f, 0.f, 0.f);
    #pragma unroll
    for (int i = 0; i < 8; i++) {
        lv[i].x = expf(lv[i].x - mx.x); sum.x += lv[i].x;
        lv[i].y = expf(lv[i].y - mx.y); sum.y += lv[i].y;
        lv[i].z = expf(lv[i].z - mx.z); sum.z += lv[i].z;
        lv[i].w = expf(lv[i].w - mx.w); sum.w += lv[i].w;
    }
    red[tid] = sum; __syncthreads();
    for (int s = 256; s > 0; s >>= 1) {
        if (tid < s) {
            float4 o = red[tid + s];
            red[tid].x += o.x; red[tid].y += o.y; red[tid].z += o.z; red[tid].w += o.w;
        }
        __syncthreads();
    }
    float4 isum = red[0];
    isum.x = 1.f / isum.x; isum.y = 1.f / isum.y; isum.z = 1.f / isum.z; isum.w = 1.f / isum.w;
    __syncthreads();
    #pragma unroll
    for (int i = 0; i < 8; i++) {
        int n = tid + i * 512;
        float4 o;
        o.x = lv[i].x * isum.x; o.y = lv[i].y * isum.y;
        o.z = lv[i].z * isum.z; o.w = lv[i].w * isum.w;
        rw4[n] = o;
        float rwsum = __fadd_rn(__fadd_rn(__fadd_rn(o.x, o.y), o.z), o.w);
        int gi = b * NN + n;
        g_uw[gi] = __fadd_rn(__fadd_rn(__fmul_rn(GAMMA, g_uw[gi]), rwsum), g_wws[gi]);
    }
    g_outputs[((size_t)b * SEQ + ts) * 1024 + 512 + tid] = 0.f;
}

__device__ void readvec_final(int ustart, int ustride, int t_out,
                              const float4* __restrict__ rw4,
                              float* sbuf, int tid) {
    int q = tid >> 5, lane = tid & 31;
    for (int u = ustart; u < 512; u += ustride) {
        int b = u >> 3, s = u & 7;
        const float4* rwb = rw4 + (size_t)b * NN;
        float4 a0 = make_float4(0,0,0,0), a1 = a0, a2 = a0, a3 = a0;
        for (int i = 0; i < 32; i += 4) {
            int n0 = s * 512 + i * 16 + q;
            const float4 v0 = __ldcs((const float4*)(g_mem + (((size_t)b * NN + n0)      << 7) + (lane << 2)));
            const float4 v1 = __ldcs((const float4*)(g_mem + (((size_t)b * NN + n0 + 16) << 7) + (lane << 2)));
            const float4 v2 = __ldcs((const float4*)(g_mem + (((size_t)b * NN + n0 + 32) << 7) + (lane << 2)));
            const float4 v3 = __ldcs((const float4*)(g_mem + (((size_t)b * NN + n0 + 48) << 7) + (lane << 2)));
            const float4 w0 = rwb[n0];
            const float4 w1 = rwb[n0 + 16];
            const float4 w2 = rwb[n0 + 32];
            const float4 w3 = rwb[n0 + 48];
            a0.x += w0.x*v0.x; a0.y += w0.x*v0.y; a0.z += w0.x*v0.z; a0.w += w0.x*v0.w;
            a1.x += w0.y*v0.x; a1.y += w0.y*v0.y; a1.z += w0.y*v0.z; a1.w += w0.y*v0.w;
            a2.x += w0.z*v0.x; a2.y += w0.z*v0.y; a2.z += w0.z*v0.z; a2.w += w0.z*v0.w;
            a3.x += w0.w*v0.x; a3.y += w0.w*v0.y; a3.z += w0.w*v0.z; a3.w += w0.w*v0.w;
            a0.x += w1.x*v1.x; a0.y += w1.x*v1.y; a0.z += w1.x*v1.z; a0.w += w1.x*v1.w;
            a1.x += w1.y*v1.x; a1.y += w1.y*v1.y; a1.z += w1.y*v1.z; a1.w += w1.y*v1.w;
            a2.x += w1.z*v1.x; a2.y += w1.z*v1.y; a2.z += w1.z*v1.z; a2.w += w1.z*v1.w;
            a3.x += w1.w*v1.x; a3.y += w1.w*v1.y; a3.z += w1.w*v1.z; a3.w += w1.w*v1.w;
            a0.x += w2.x*v2.x; a0.y += w2.x*v2.y; a0.z += w2.x*v2.z; a0.w += w2.x*v2.w;
            a1.x += w2.y*v2.x; a1.y += w2.y*v2.y; a1.z += w2.y*v2.z; a1.w += w2.y*v2.w;
            a2.x += w2.z*v2.x; a2.y += w2.z*v2.y; a2.z += w2.z*v2.z; a2.w += w2.z*v2.w;
            a3.x += w2.w*v2.x; a3.y += w2.w*v2.y; a3.z += w2.w*v2.z; a3.w += w2.w*v2.w;
            a0.x += w3.x*v3.x; a0.y += w3.x*v3.y; a0.z += w3.x*v3.z; a0.w += w3.x*v3.w;
            a1.x += w3.y*v3.x; a1.y += w3.y*v3.y; a1.z += w3.y*v3.z; a1.w += w3.y*v3.w;
            a2.x += w3.z*v3.x; a2.y += w3.z*v3.y; a2.z += w3.z*v3.z; a2.w += w3.z*v3.w;
            a3.x += w3.w*v3.x; a3.y += w3.w*v3.y; a3.z += w3.w*v3.z; a3.w += w3.w*v3.w;
        }
        ((float4*)sbuf)[(q * 4 + 0) * 32 + lane] = a0;
        ((float4*)sbuf)[(q * 4 + 1) * 32 + lane] = a1;
        ((float4*)sbuf)[(q * 4 + 2) * 32 + lane] = a2;
        ((float4*)sbuf)[(q * 4 + 3) * 32 + lane] = a3;
        __syncthreads();
        {
            int r = tid >> 7, m = tid & 127;
            float vsum = 0.f;
            #pragma unroll
            for (int qq = 0; qq < 16; qq++) vsum += sbuf[(qq * 4 + r) * 128 + m];
            atomicAdd(&g_outputs[((size_t)b * SEQ + t_out) * 1024 + 512 + tid], vsum);
        }
        __syncthreads();
    }
}

__global__ __launch_bounds__(TPB, 1) void k_persist(
    const float* __restrict__ x, const float* __restrict__ y,
    const float* __restrict__ Wl, const float* __restrict__ bl,
    const float* __restrict__ Wm, const float* __restrict__ bm)
{
    __shared__ __align__(16) float sbuf[8448];
    const int tid = threadIdx.x;
    const int bx  = blockIdx.x;

    for (int t = 0; t < SEQ; t++) {
        const int p = t & 1;
        // merged prelude: [0..63] softmax+uw(t-1) -> idx(t); [64..127] gemm(t) -> query(t)
        if (bx < 64) {
            if (t > 0) {
                softmax_uw_phase(g_rwbuf[p], bx, t - 1, sbuf, tid);
                __syncthreads();
            }
            idx_phase(bx, sbuf, tid);
        } else if (bx < 128) {
            gemm_gates(x, y, Wl, bl, t, sbuf, tid, bx - 64);
            __syncthreads();
            if (tid == 0) {
                int prev;
                asm volatile("atom.acq_rel.gpu.global.add.u32 %0, [%1], %2;"
                             : "=r"(prev) : "l"(&g_gcnt[p]), "r"(1u) : "memory");
                int v;
                do { asm volatile("ld.acquire.gpu.u32 %0, [%1];" : "=r"(v) : "l"(&g_gcnt[p])); }
                while (v < 64);
            }
            __syncthreads();
            query_phase(bx - 64, t, Wm, bm, sbuf, tid);
        }
        grid_sync();
        // update(t) + readvec(t-1) + dots + ||mem||^2 + ww sums (all blocks)
        update_phase((const float4*)g_rwbuf[p], bx, tid, sbuf, t);
        grid_sync();
    }
    if (bx < 64) softmax_uw_phase(g_rwbuf[SEQ & 1], bx, SEQ - 1, sbuf, tid);
    grid_sync();
    readvec_final(bx, NBLK, SEQ - 1, (const float4*)g_rwbuf[SEQ & 1], sbuf, tid);
}

__global__ __launch_bounds__(512) void k_probs(const float* __restrict__ Wf,
                                               const float* __restrict__ bf,
                                               float* __restrict__ out) {
    int g0 = blockIdx.x * 8;
    int tid = threadIdx.x;
    int row = tid >> 6, j = tid & 63;
    __shared__ float sin_[8][1024];
    for (int e = tid; e < 8192; e += 512)
        sin_[e >> 10][e & 1023] = g_outputs[(size_t)(g0 + (e >> 10)) * 1024 + (e & 1023)];
    __syncthreads();
    float acc = bf[j];
    #pragma unroll 8
    for (int k = 0; k < 1024; k++) acc += sin_[row][k] * Wf[k * 64 + j];
    __shared__ float lg[8][64];
    lg[row][j] = acc;
    __syncthreads();
    float mx = -FLT_MAX;
    #pragma unroll
    for (int q = 0; q < 64; q++) mx = fmaxf(mx, lg[row][q]);
    float sum = 0.f;
    #pragma unroll
    for (int q = 0; q < 64; q++) sum += expf(lg[row][q] - mx);
    out[(size_t)(g0 + row) * 64 + j] = expf(acc - mx) / sum;
}

// ---------------- vectorized copy of final states to output ---------------------
__global__ void k_final(float* __restrict__ out) {
    long tid = (long)blockIdx.x * blockDim.x + threadIdx.x;
    long stride = (long)gridDim.x * blockDim.x;
    const long P = (long)BSZ * SEQ * NOUT;
    const long MEMN = (long)BSZ * NN * MM;
    const long RWN = (long)BSZ * RHEAD * NN;
    float* pm = out + P;
    float* pr = pm + MEMN;
    float* pu = pr + RWN;
    const float4* rwfin4 = (const float4*)g_rwbuf[SEQ & 1];
    const float4* mem4 = (const float4*)g_mem;
    float4* pm4 = (float4*)pm;
    for (long i = tid; i < MEMN / 4; i += stride) pm4[i] = mem4[i];
    for (long i = tid; i < (long)BSZ*NN; i += stride) {
        long b = i >> 12, n = i & 4095;
        float4 v = rwfin4[i];
        float* rp = pr + ((b << 2) << 12) + n;
        rp[0]      = v.x;
        rp[NN]     = v.y;
        rp[2 * NN] = v.z;
        rp[3 * NN] = v.w;
    }
    const float4* uw4 = (const float4*)g_uw;
    float4* pu4 = (float4*)pu;
    for (long i = tid; i < (long)BSZ*NN/4; i += stride) pu4[i] = uw4[i];
}

extern "C" void kernel_launch(void* const* d_in, const int* in_sizes, int n_in,
                              void* d_out, int out_size) {
    const float* x     = (const float*)d_in[0];
    const float* y     = (const float*)d_in[1];
    const float* mem   = (const float*)d_in[2];
    const float* rw    = (const float*)d_in[3];
    const float* uw    = (const float*)d_in[4];
    const float* Wl    = (const float*)d_in[5];
    const float* bl    = (const float*)d_in[6];
    const float* Wm    = (const float*)d_in[7];
    const float* bm    = (const float*)d_in[8];
    const float* Wf    = (const float*)d_in[9];
    const float* bf    = (const float*)d_in[10];
    const float* alpha = (const float*)d_in[11];
    float* out = (float*)d_out;

    k_init<<<4096, 256>>>(mem, rw, uw, alpha);
    k_persist<<<NBLK, TPB>>>(x, y, Wl, bl, Wm, bm);
    k_probs<<<1024, 512>>>(Wf, bf, out);

    long total = 524288L + 33554432L + 1048576L + 262144L;
    if ((long)out_size >= total) {
        k_final<<<8192, 256>>>(out);
    }
}

// round 15
// speedup vs baseline: 1.0207x; 1.0207x over previous
#include <cuda_runtime.h>
#include <math.h>
#include <float.h>

#define BSZ   64
#define SEQ   128
#define INP   256
#define HH    512
#define NN    4096
#define MM    128
#define RHEAD 4
#define NOUT  64
#define GAMMA 0.95f
#define KTOT  769
#define NBLK  148
#define TPB   512
#define NROWS (BSZ*NN)
#define RPW   111

typedef unsigned long long ull;

__device__ __align__(16) float g_mem[(size_t)BSZ*NN*MM];
__device__ __align__(16) float g_rwbuf[2][BSZ*RHEAD*NN];
__device__ __align__(16) float g_uw[BSZ*NN];
__device__ float g_wws[BSZ*NN];
__device__ __align__(16) float g_dots[BSZ*RHEAD*NN];
__device__ float g_query[BSZ*HH];
__device__ float g_hid[2][BSZ*HH];
__device__ float g_cell[BSZ*HH];
__device__ float g_outputs[(size_t)BSZ*SEQ*1024];
__device__ float g_alpha_s[BSZ*RHEAD];
__device__ int   g_idx[BSZ*RHEAD];
__device__ float g_q2a[2];
__device__ float g_m2a[2];
__device__ int   g_gcnt[2];
__device__ __align__(128) unsigned g_bar_cnt = 0;
__device__ __align__(128) unsigned g_bar_gen = 0;

// ---------------- packed f32x2 helpers (per-lane IEEE ops, bit-identical) -----
__device__ __forceinline__ ull pk2(float a, float b) {
    ull r; asm("mov.b64 %0, {%1,%2};" : "=l"(r) : "f"(a), "f"(b)); return r;
}
__device__ __forceinline__ void upk2(ull p, float& a, float& b) {
    asm("mov.b64 {%0,%1}, %2;" : "=f"(a), "=f"(b) : "l"(p));
}
__device__ __forceinline__ ull fma2_(ull a, ull b, ull c) {
    ull d; asm("fma.rn.f32x2 %0, %1, %2, %3;" : "=l"(d) : "l"(a), "l"(b), "l"(c)); return d;
}
__device__ __forceinline__ ull mul2_(ull a, ull b) {
    ull d; asm("mul.rn.f32x2 %0, %1, %2;" : "=l"(d) : "l"(a), "l"(b)); return d;
}
__device__ __forceinline__ ull add2_(ull a, ull b) {
    ull d; asm("add.rn.f32x2 %0, %1, %2;" : "=l"(d) : "l"(a), "l"(b)); return d;
}

struct UCtx {
    float4 ql0, ql1, ql2, ql3;
    ull q0xy, q0zw, q1xy, q1zw, q2xy, q2zw, q3xy, q3zw;
    float as0, as1, as2, as3, wc0, wc1, wc2, wc3;
    int ix0, ix1, ix2, ix3;
};
struct UAcc {
    ull rv0xy, rv0zw, rv1xy, rv1zw, rv2xy, rv2zw, rv3xy, rv3zw;
    ull m2a, m2b;
};

__device__ __forceinline__ void grid_sync() {
    __syncthreads();
    if (threadIdx.x == 0) {
        unsigned gen;
        asm volatile("ld.acquire.gpu.u32 %0, [%1];" : "=r"(gen) : "l"(&g_bar_gen));
        unsigned prev;
        asm volatile("atom.acq_rel.gpu.global.add.u32 %0, [%1], %2;"
                     : "=r"(prev) : "l"(&g_bar_cnt), "r"(1u) : "memory");
        if (prev == (unsigned)gridDim.x - 1u) {
            asm volatile("st.relaxed.gpu.u32 [%0], %1;" :: "l"(&g_bar_cnt), "r"(0u) : "memory");
            asm volatile("red.release.gpu.global.add.u32 [%0], %1;" :: "l"(&g_bar_gen), "r"(1u) : "memory");
        } else {
            unsigned cur;
            do {
                asm volatile("ld.acquire.gpu.u32 %0, [%1];" : "=r"(cur) : "l"(&g_bar_gen));
            } while (cur == gen);
        }
    }
    __syncthreads();
}

// ---------------- init: vectorized copies into scratch --------------------------
__global__ void k_init(const float* __restrict__ mem_in,
                       const float* __restrict__ rw_in,
                       const float* __restrict__ uw_in,
                       const float* __restrict__ alpha) {
    long tid = (long)blockIdx.x * blockDim.x + threadIdx.x;
    long stride = (long)gridDim.x * blockDim.x;
    const long MEM4 = (long)BSZ*NN*MM/4;
    const float4* src4 = (const float4*)mem_in;
    float4* dst4 = (float4*)g_mem;
    for (long i = tid; i < MEM4; i += stride) dst4[i] = src4[i];
    float4* rwi = (float4*)g_rwbuf[0];
    for (long i = tid; i < (long)BSZ*NN; i += stride) {
        long b = i >> 12, n = i & 4095;
        const float* rp = rw_in + ((b << 2) << 12) + n;
        float4 v;
        v.x = rp[0];
        v.y = rp[NN];
        v.z = rp[2 * NN];
        v.w = rp[3 * NN];
        rwi[i] = v;
    }
    const long UW4 = (long)BSZ*NN/4;
    const float4* us4 = (const float4*)uw_in;
    float4* ud4 = (float4*)g_uw;
    for (long i = tid; i < UW4; i += stride) ud4[i] = us4[i];
    if (tid < BSZ*RHEAD) g_alpha_s[tid] = 1.0f / (1.0f + expf(-alpha[tid]));
}

__device__ void gemm_gates(const float* __restrict__ x, const float* __restrict__ y,
                           const float* __restrict__ Wl, const float* __restrict__ bl,
                           int t, float* sbuf, int tid, int jblk) {
    float* As = sbuf;
    float* Bs = sbuf + 2112;
    float* Ps = sbuf + 3136;
    const int j0 = jblk * 8;
    const int row = tid >> 3;
    const int cg  = tid & 7;
    const float* hprev = g_hid[(t & 1) ^ 1];

    float acc[4] = {0.f, 0.f, 0.f, 0.f};

    for (int kb = 0; kb < KTOT; kb += 32) {
        #pragma unroll
        for (int i = 0; i < 4; i++) {
            int e = tid + i * 512;
            int r = e >> 5, k = e & 31;
            int kg = kb + k;
            float v = 0.f;
            if (kg < INP) v = x[(r * SEQ + t) * INP + kg];
            else if (kg == INP) { if (t > 0) v = y[r * SEQ + t - 1]; }
            else if (kg < KTOT) { if (t > 0) v = hprev[r * HH + kg - INP - 1]; }
            As[r * 33 + k] = v;
        }
        #pragma unroll
        for (int i = 0; i < 2; i++) {
            int e = tid + i * 512;
            int k = e >> 5, c = e & 31;
            int kg = kb + k;
            float v = 0.f;
            if (kg < KTOT) {
                int g = c >> 3, jj = c & 7;
                v = Wl[kg * (4 * HH) + g * HH + j0 + jj];
            }
            Bs[k * 32 + c] = v;
        }
        __syncthreads();
        #pragma unroll
        for (int k = 0; k < 32; k++) {
            float a = As[row * 33 + k];
            float4 bv = *(const float4*)&Bs[k * 32 + cg * 4];
            acc[0] += a * bv.x; acc[1] += a * bv.y; acc[2] += a * bv.z; acc[3] += a * bv.w;
        }
        __syncthreads();
    }
    #pragma unroll
    for (int i = 0; i < 4; i++) Ps[row * 32 + cg * 4 + i] = acc[i];
    __syncthreads();

    float* hcur = g_hid[t & 1];
    {
        int b = tid >> 3, jj = tid & 7;
        int j = j0 + jj;
        float pf = Ps[b * 32 +  0 + jj] + bl[0 * HH + j];
        float pi = Ps[b * 32 +  8 + jj] + bl[1 * HH + j];
        float po = Ps[b * 32 + 16 + jj] + bl[2 * HH + j];
        float pu = Ps[b * 32 + 24 + jj] + bl[3 * HH + j];
        float f  = 1.f / (1.f + expf(-pf));
        float ig = 1.f / (1.f + expf(-pi));
        float o  = 1.f / (1.f + expf(-po));
        float uu = tanhf(pu);
        float cprev = (t > 0) ? g_cell[b * HH + j] : 0.f;
        float c = f * cprev + ig * uu;
        float h = o * tanhf(c);
        g_cell[b * HH + j] = c;
        hcur[b * HH + j] = h;
        g_outputs[((size_t)b * SEQ + t) * 1024 + j] = h;
    }
}

__device__ void query_phase(int b, int t, const float* __restrict__ Wm,
                            const float* __restrict__ bm, float* sbuf, int tid) {
    const float* h = g_hid[t & 1] + b * HH;
    sbuf[tid] = h[tid];
    __syncthreads();
    float a0 = 0.f, a1 = 0.f, a2 = 0.f, a3 = 0.f;
    #pragma unroll 4
    for (int k = 0; k < HH; k += 4) {
        a0 += sbuf[k]     * Wm[(k)     * HH + tid];
        a1 += sbuf[k + 1] * Wm[(k + 1) * HH + tid];
        a2 += sbuf[k + 2] * Wm[(k + 2) * HH + tid];
        a3 += sbuf[k + 3] * Wm[(k + 3) * HH + tid];
    }
    float qv = a0 + a1 + a2 + a3 + bm[tid];
    g_query[b * HH + tid] = qv;
    float* red = sbuf + 1024;
    red[tid] = qv * qv;
    __syncthreads();
    for (int s = 256; s > 0; s >>= 1) {
        if (tid < s) red[tid] += red[tid + s];
        __syncthreads();
    }
    if (tid == 0) atomicAdd(&g_q2a[t & 1], red[0]);
}

// ---------------- idx: identical 4-pass reduction, candidates from registers -----
__device__ void idx_phase(int b, float* sbuf, int tid, const float* uwv) {
    float v[8]; int nn[8];
    #pragma unroll
    for (int i = 0; i < 8; i++) { int n = tid + i * 512; v[i] = uwv[i]; nn[i] = n; }
    float* sval = sbuf;
    int*   sidx = (int*)(sbuf + 512);
    for (int sel = 0; sel < 4; sel++) {
        float bv = FLT_MAX; int bn = 0x7fffffff;
        #pragma unroll
        for (int i = 0; i < 8; i++)
            if (v[i] < bv || (v[i] == bv && nn[i] < bn)) { bv = v[i]; bn = nn[i]; }
        sval[tid] = bv; sidx[tid] = bn;
        __syncthreads();
        for (int s = 256; s > 0; s >>= 1) {
            if (tid < s) {
                float ov = sval[tid + s]; int on = sidx[tid + s];
                if (ov < sval[tid] || (ov == sval[tid] && on < sidx[tid])) {
                    sval[tid] = ov; sidx[tid] = on;
                }
            }
            __syncthreads();
        }
        int win = sidx[0];
        if (tid == 0) g_idx[b * 4 + sel] = win;
        __syncthreads();
        #pragma unroll
        for (int i = 0; i < 8; i++) if (nn[i] == win) v[i] = FLT_MAX;
    }
}

// ---------------- per-row fused body ---------------------------------------------
__device__ __forceinline__ void urow(int row, float4 v, float4 a,
                                     const UCtx& C, UAcc& A, int lane) {
    ull vxy = pk2(v.x, v.y), vzw = pk2(v.z, v.w);
    ull t;
    t = pk2(a.x, a.x); A.rv0xy = fma2_(t, vxy, A.rv0xy); A.rv0zw = fma2_(t, vzw, A.rv0zw);
    t = pk2(a.y, a.y); A.rv1xy = fma2_(t, vxy, A.rv1xy); A.rv1zw = fma2_(t, vzw, A.rv1zw);
    t = pk2(a.z, a.z); A.rv2xy = fma2_(t, vxy, A.rv2xy); A.rv2zw = fma2_(t, vzw, A.rv2zw);
    t = pk2(a.w, a.w); A.rv3xy = fma2_(t, vxy, A.rv3xy); A.rv3zw = fma2_(t, vzw, A.rv3zw);

    int n = row & 4095;
    float w0 = __fmul_rn(C.as0, a.x); if (C.ix0 == n) w0 = __fadd_rn(w0, C.wc0);
    float w1 = __fmul_rn(C.as1, a.y); if (C.ix1 == n) w1 = __fadd_rn(w1, C.wc1);
    float w2 = __fmul_rn(C.as2, a.z); if (C.ix2 == n) w2 = __fadd_rn(w2, C.wc2);
    float w3 = __fmul_rn(C.as3, a.w); if (C.ix3 == n) w3 = __fadd_rn(w3, C.wc3);
    ull w0p = pk2(w0, w0), w1p = pk2(w1, w1), w2p = pk2(w2, w2), w3p = pk2(w3, w3);
    ull sxy = fma2_(w3p, C.q3xy, fma2_(w2p, C.q2xy, fma2_(w1p, C.q1xy, mul2_(w0p, C.q0xy))));
    ull szw = fma2_(w3p, C.q3zw, fma2_(w2p, C.q2zw, fma2_(w1p, C.q1zw, mul2_(w0p, C.q0zw))));
    vxy = add2_(vxy, sxy);
    vzw = add2_(vzw, szw);
    upk2(vxy, v.x, v.y);
    upk2(vzw, v.z, v.w);
    __stcs((float4*)(g_mem + ((size_t)row << 7) + (lane << 2)), v);

    float d0 = C.ql0.x*v.x + C.ql0.y*v.y + C.ql0.z*v.z + C.ql0.w*v.w;
    float d1 = C.ql1.x*v.x + C.ql1.y*v.y + C.ql1.z*v.z + C.ql1.w*v.w;
    float d2 = C.ql2.x*v.x + C.ql2.y*v.y + C.ql2.z*v.z + C.ql2.w*v.w;
    float d3 = C.ql3.x*v.x + C.ql3.y*v.y + C.ql3.z*v.z + C.ql3.w*v.w;
    d0 += __shfl_xor_sync(0xffffffffu, d0, 16);
    d1 += __shfl_xor_sync(0xffffffffu, d1, 16);
    d2 += __shfl_xor_sync(0xffffffffu, d2, 16);
    d3 += __shfl_xor_sync(0xffffffffu, d3, 16);
    d0 += __shfl_xor_sync(0xffffffffu, d0, 8);
    d1 += __shfl_xor_sync(0xffffffffu, d1, 8);
    d2 += __shfl_xor_sync(0xffffffffu, d2, 8);
    d3 += __shfl_xor_sync(0xffffffffu, d3, 8);
    int g = lane >> 3;
    float dv = (g == 0) ? d0 : (g == 1) ? d1 : (g == 2) ? d2 : d3;
    dv += __shfl_xor_sync(0xffffffffu, dv, 4);
    dv += __shfl_xor_sync(0xffffffffu, dv, 2);
    dv += __shfl_xor_sync(0xffffffffu, dv, 1);
    if ((lane & 7) == 0) g_dots[((size_t)row << 2) + g] = dv;
    if (lane == 0) g_wws[row] = __fadd_rn(__fadd_rn(__fadd_rn(w0, w1), w2), w3);
    A.m2a = fma2_(vxy, vxy, A.m2a);
    A.m2b = fma2_(vzw, vzw, A.m2b);
}

__device__ __forceinline__ void u_group8(int row, const float4* __restrict__ rw4,
                                         const UCtx& C, UAcc& A, int lane) {
    float4 v0 = __ldcs((const float4*)(g_mem + ((size_t)(row    ) << 7) + (lane << 2)));
    float4 v1 = __ldcs((const float4*)(g_mem + ((size_t)(row + 1) << 7) + (lane << 2)));
    float4 v2 = __ldcs((const float4*)(g_mem + ((size_t)(row + 2) << 7) + (lane << 2)));
    float4 v3 = __ldcs((const float4*)(g_mem + ((size_t)(row + 3) << 7) + (lane << 2)));
    float4 v4 = __ldcs((const float4*)(g_mem + ((size_t)(row + 4) << 7) + (lane << 2)));
    float4 v5 = __ldcs((const float4*)(g_mem + ((size_t)(row + 5) << 7) + (lane << 2)));
    float4 v6 = __ldcs((const float4*)(g_mem + ((size_t)(row + 6) << 7) + (lane << 2)));
    float4 v7 = __ldcs((const float4*)(g_mem + ((size_t)(row + 7) << 7) + (lane << 2)));
    urow(row,     v0, rw4[row    ], C, A, lane);
    urow(row + 1, v1, rw4[row + 1], C, A, lane);
    urow(row + 2, v2, rw4[row + 2], C, A, lane);
    urow(row + 3, v3, rw4[row + 3], C, A, lane);
    urow(row + 4, v4, rw4[row + 4], C, A, lane);
    urow(row + 5, v5, rw4[row + 5], C, A, lane);
    urow(row + 6, v6, rw4[row + 6], C, A, lane);
    urow(row + 7, v7, rw4[row + 7], C, A, lane);
}

__device__ void update_phase(const float4* __restrict__ rw4, int bx, int tid,
                             float* sbuf, int t) {
    const int p = t & 1;
    if (bx == 147 && tid == 0) { g_q2a[p ^ 1] = 0.f; g_m2a[p ^ 1] = 0.f; }
    if (bx == 146 && tid == 0) { g_gcnt[p] = 0; }
    int lane = tid & 31;
    int w = bx * 16 + (tid >> 5);
    int r0 = w * RPW;
    int r1 = r0 + RPW; if (r1 > NROWS) r1 = NROWS;
    UAcc A;
    A.m2a = 0ull; A.m2b = 0ull;
    int row = r0;
    while (row < r1) {
        int b = row >> 12;
        int bend = (b + 1) << 12; if (bend > r1) bend = r1;
        UCtx C;
        const float* qb = g_query + b * HH;
        C.ql0 = *(const float4*)(qb + 0 * 128 + lane * 4);
        C.ql1 = *(const float4*)(qb + 1 * 128 + lane * 4);
        C.ql2 = *(const float4*)(qb + 2 * 128 + lane * 4);
        C.ql3 = *(const float4*)(qb + 3 * 128 + lane * 4);
        C.q0xy = pk2(C.ql0.x, C.ql0.y); C.q0zw = pk2(C.ql0.z, C.ql0.w);
        C.q1xy = pk2(C.ql1.x, C.ql1.y); C.q1zw = pk2(C.ql1.z, C.ql1.w);
        C.q2xy = pk2(C.ql2.x, C.ql2.y); C.q2zw = pk2(C.ql2.z, C.ql2.w);
        C.q3xy = pk2(C.ql3.x, C.ql3.y); C.q3zw = pk2(C.ql3.z, C.ql3.w);
        C.as0 = g_alpha_s[b*4+0]; C.as1 = g_alpha_s[b*4+1];
        C.as2 = g_alpha_s[b*4+2]; C.as3 = g_alpha_s[b*4+3];
        C.wc0 = 1.f - C.as0; C.wc1 = 1.f - C.as1; C.wc2 = 1.f - C.as2; C.wc3 = 1.f - C.as3;
        C.ix0 = g_idx[b*4+0]; C.ix1 = g_idx[b*4+1];
        C.ix2 = g_idx[b*4+2]; C.ix3 = g_idx[b*4+3];
        A.rv0xy = 0ull; A.rv0zw = 0ull; A.rv1xy = 0ull; A.rv1zw = 0ull;
        A.rv2xy = 0ull; A.rv2zw = 0ull; A.rv3xy = 0ull; A.rv3zw = 0ull;
        for (; row + 8 <= bend; row += 8)
            u_group8(row, rw4, C, A, lane);
        for (; row < bend; row++) {
            float4 v = __ldcs((const float4*)(g_mem + ((size_t)row << 7) + (lane << 2)));
            urow(row, v, rw4[row], C, A, lane);
        }
        if (t > 0) {
            float4 rv0, rv1, rv2, rv3;
            upk2(A.rv0xy, rv0.x, rv0.y); upk2(A.rv0zw, rv0.z, rv0.w);
            upk2(A.rv1xy, rv1.x, rv1.y); upk2(A.rv1zw, rv1.z, rv1.w);
            upk2(A.rv2xy, rv2.x, rv2.y); upk2(A.rv2zw, rv2.z, rv2.w);
            upk2(A.rv3xy, rv3.x, rv3.y); upk2(A.rv3zw, rv3.z, rv3.w);
            float* dst = g_outputs + ((size_t)b * SEQ + (t - 1)) * 1024 + 512 + lane * 4;
            atomicAdd(dst + 0,       rv0.x); atomicAdd(dst + 1,       rv0.y);
            atomicAdd(dst + 2,       rv0.z); atomicAdd(dst + 3,       rv0.w);
            atomicAdd(dst + 128 + 0, rv1.x); atomicAdd(dst + 128 + 1, rv1.y);
            atomicAdd(dst + 128 + 2, rv1.z); atomicAdd(dst + 128 + 3, rv1.w);
            atomicAdd(dst + 256 + 0, rv2.x); atomicAdd(dst + 256 + 1, rv2.y);
            atomicAdd(dst + 256 + 2, rv2.z); atomicAdd(dst + 256 + 3, rv2.w);
            atomicAdd(dst + 384 + 0, rv3.x); atomicAdd(dst + 384 + 1, rv3.y);
            atomicAdd(dst + 384 + 2, rv3.z); atomicAdd(dst + 384 + 3, rv3.w);
        }
    }
    float m2;
    {
        float ax, ay, bx2, by;
        upk2(A.m2a, ax, ay);
        upk2(A.m2b, bx2, by);
        m2 = (ax + ay) + (bx2 + by);
    }
    #pragma unroll
    for (int o = 16; o > 0; o >>= 1) m2 += __shfl_xor_sync(0xffffffffu, m2, o);
    if (lane == 0) sbuf[tid >> 5] = m2;
    __syncthreads();
    if (tid < 16) {
        float v = sbuf[tid];
        #pragma unroll
        for (int o = 8; o > 0; o >>= 1) v += __shfl_xor_sync(0x0000ffffu, v, o);
        if (tid == 0) atomicAdd(&g_m2a[p], v);
    }
}

// ---------------- softmax(ts) + uw(ts); uw values handed back in registers -------
__device__ void softmax_uw_phase(float* __restrict__ rwn, int b, int ts,
                                 float* sbuf, int tid, float* uwv) {
    float inv = 1.f / __fmul_rn(sqrtf(g_q2a[ts & 1]), sqrtf(g_m2a[ts & 1]));
    const float4* D = (const float4*)g_dots + (size_t)b * NN;
    float4* rw4 = (float4*)rwn + (size_t)b * NN;
    float4* red = (float4*)sbuf;
    float4 lv[8];
    float4 mx = make_float4(-FLT_MAX, -FLT_MAX, -FLT_MAX, -FLT_MAX);
    #pragma unroll
    for (int i = 0; i < 8; i++) {
        float4 d = D[tid + i * 512];
        lv[i].x = d.x * inv; lv[i].y = d.y * inv; lv[i].z = d.z * inv; lv[i].w = d.w * inv;
        mx.x = fmaxf(mx.x, lv[i].x); mx.y = fmaxf(mx.y, lv[i].y);
        mx.z = fmaxf(mx.z, lv[i].z); mx.w = fmaxf(mx.w, lv[i].w);
    }
    red[tid] = mx; __syncthreads();
    for (int s = 256; s > 0; s >>= 1) {
        if (tid < s) {
            float4 o = red[tid + s];
            red[tid].x = fmaxf(red[tid].x, o.x); red[tid].y = fmaxf(red[tid].y, o.y);
            red[tid].z = fmaxf(red[tid].z, o.z); red[tid].w = fmaxf(red[tid].w, o.w);
        }
        __syncthreads();
    }
    mx = red[0]; __syncthreads();
    float4 sum = make_float4(0.f, 0.f, 0.f, 0.f);
    #pragma unroll
    for (int i = 0; i < 8; i++) {
        lv[i].x = expf(lv[i].x - mx.x); sum.x += lv[i].x;
        lv[i].y = expf(lv[i].y - mx.y); sum.y += lv[i].y;
        lv[i].z = expf(lv[i].z - mx.z); sum.z += lv[i].z;
        lv[i].w = expf(lv[i].w - mx.w); sum.w += lv[i].w;
    }
    red[tid] = sum; __syncthreads();
    for (int s = 256; s > 0; s >>= 1) {
        if (tid < s) {
            float4 o = red[tid + s];
            red[tid].x += o.x; red[tid].y += o.y; red[tid].z += o.z; red[tid].w += o.w;
        }
        __syncthreads();
    }
    float4 isum = red[0];
    isum.x = 1.f / isum.x; isum.y = 1.f / isum.y; isum.z = 1.f / isum.z; isum.w = 1.f / isum.w;
    __syncthreads();
    #pragma unroll
    for (int i = 0; i < 8; i++) {
        int n = tid + i * 512;
        float4 o;
        o.x = lv[i].x * isum.x; o.y = lv[i].y * isum.y;
        o.z = lv[i].z * isum.z; o.w = lv[i].w * isum.w;
        rw4[n] = o;
        float rwsum = __fadd_rn(__fadd_rn(__fadd_rn(o.x, o.y), o.z), o.w);
        int gi = b * NN + n;
        float uwn = __fadd_rn(__fadd_rn(__fmul_rn(GAMMA, g_uw[gi]), rwsum), g_wws[gi]);
        g_uw[gi] = uwn;
        uwv[i] = uwn;
    }
    g_outputs[((size_t)b * SEQ + ts) * 1024 + 512 + tid] = 0.f;
}

__device__ void readvec_final(int ustart, int ustride, int t_out,
                              const float4* __restrict__ rw4,
                              float* sbuf, int tid) {
    int q = tid >> 5, lane = tid & 31;
    for (int u = ustart; u < 512; u += ustride) {
        int b = u >> 3, s = u & 7;
        const float4* rwb = rw4 + (size_t)b * NN;
        float4 a0 = make_float4(0,0,0,0), a1 = a0, a2 = a0, a3 = a0;
        for (int i = 0; i < 32; i += 4) {
            int n0 = s * 512 + i * 16 + q;
            const float4 v0 = __ldcs((const float4*)(g_mem + (((size_t)b * NN + n0)      << 7) + (lane << 2)));
            const float4 v1 = __ldcs((const float4*)(g_mem + (((size_t)b * NN + n0 + 16) << 7) + (lane << 2)));
            const float4 v2 = __ldcs((const float4*)(g_mem + (((size_t)b * NN + n0 + 32) << 7) + (lane << 2)));
            const float4 v3 = __ldcs((const float4*)(g_mem + (((size_t)b * NN + n0 + 48) << 7) + (lane << 2)));
            const float4 w0 = rwb[n0];
            const float4 w1 = rwb[n0 + 16];
            const float4 w2 = rwb[n0 + 32];
            const float4 w3 = rwb[n0 + 48];
            a0.x += w0.x*v0.x; a0.y += w0.x*v0.y; a0.z += w0.x*v0.z; a0.w += w0.x*v0.w;
            a1.x += w0.y*v0.x; a1.y += w0.y*v0.y; a1.z += w0.y*v0.z; a1.w += w0.y*v0.w;
            a2.x += w0.z*v0.x; a2.y += w0.z*v0.y; a2.z += w0.z*v0.z; a2.w += w0.z*v0.w;
            a3.x += w0.w*v0.x; a3.y += w0.w*v0.y; a3.z += w0.w*v0.z; a3.w += w0.w*v0.w;
            a0.x += w1.x*v1.x; a0.y += w1.x*v1.y; a0.z += w1.x*v1.z; a0.w += w1.x*v1.w;
            a1.x += w1.y*v1.x; a1.y += w1.y*v1.y; a1.z += w1.y*v1.z; a1.w += w1.y*v1.w;
            a2.x += w1.z*v1.x; a2.y += w1.z*v1.y; a2.z += w1.z*v1.z; a2.w += w1.z*v1.w;
            a3.x += w1.w*v1.x; a3.y += w1.w*v1.y; a3.z += w1.w*v1.z; a3.w += w1.w*v1.w;
            a0.x += w2.x*v2.x; a0.y += w2.x*v2.y; a0.z += w2.x*v2.z; a0.w += w2.x*v2.w;
            a1.x += w2.y*v2.x; a1.y += w2.y*v2.y; a1.z += w2.y*v2.z; a1.w += w2.y*v2.w;
            a2.x += w2.z*v2.x; a2.y += w2.z*v2.y; a2.z += w2.z*v2.z; a2.w += w2.z*v2.w;
            a3.x += w2.w*v2.x; a3.y += w2.w*v2.y; a3.z += w2.w*v2.z; a3.w += w2.w*v2.w;
            a0.x += w3.x*v3.x; a0.y += w3.x*v3.y; a0.z += w3.x*v3.z; a0.w += w3.x*v3.w;
            a1.x += w3.y*v3.x; a1.y += w3.y*v3.y; a1.z += w3.y*v3.z; a1.w += w3.y*v3.w;
            a2.x += w3.z*v3.x; a2.y += w3.z*v3.y; a2.z += w3.z*v3.z; a2.w += w3.z*v3.w;
            a3.x += w3.w*v3.x; a3.y += w3.w*v3.y; a3.z += w3.w*v3.z; a3.w += w3.w*v3.w;
        }
        ((float4*)sbuf)[(q * 4 + 0) * 32 + lane] = a0;
        ((float4*)sbuf)[(q * 4 + 1) * 32 + lane] = a1;
        ((float4*)sbuf)[(q * 4 + 2) * 32 + lane] = a2;
        ((float4*)sbuf)[(q * 4 + 3) * 32 + lane] = a3;
        __syncthreads();
        {
            int r = tid >> 7, m = tid & 127;
            float vsum = 0.f;
            #pragma unroll
            for (int qq = 0; qq < 16; qq++) vsum += sbuf[(qq * 4 + r) * 128 + m];
            atomicAdd(&g_outputs[((size_t)b * SEQ + t_out) * 1024 + 512 + tid], vsum);
        }
        __syncthreads();
    }
}

__global__ __launch_bounds__(TPB, 1) void k_persist(
    const float* __restrict__ x, const float* __restrict__ y,
    const float* __restrict__ Wl, const float* __restrict__ bl,
    const float* __restrict__ Wm, const float* __restrict__ bm)
{
    __shared__ __align__(16) float sbuf[8448];
    const int tid = threadIdx.x;
    const int bx  = blockIdx.x;

    for (int t = 0; t < SEQ; t++) {
        const int p = t & 1;
        // merged prelude: [0..63] softmax+uw(t-1) -> idx(t); [64..127] gemm(t) -> query(t)
        if (bx < 64) {
            float uwv[8];
            if (t > 0) {
                softmax_uw_phase(g_rwbuf[p], bx, t - 1, sbuf, tid, uwv);
                __syncthreads();
            } else {
                #pragma unroll
                for (int i = 0; i < 8; i++) uwv[i] = g_uw[bx * NN + tid + i * 512];
            }
            idx_phase(bx, sbuf, tid, uwv);
        } else if (bx < 128) {
            gemm_gates(x, y, Wl, bl, t, sbuf, tid, bx - 64);
            __syncthreads();
            if (tid == 0) {
                int prev;
                asm volatile("atom.acq_rel.gpu.global.add.u32 %0, [%1], %2;"
                             : "=r"(prev) : "l"(&g_gcnt[p]), "r"(1u) : "memory");
                int v;
                do { asm volatile("ld.acquire.gpu.u32 %0, [%1];" : "=r"(v) : "l"(&g_gcnt[p])); }
                while (v < 64);
            }
            __syncthreads();
            query_phase(bx - 64, t, Wm, bm, sbuf, tid);
        }
        grid_sync();
        // update(t) + readvec(t-1) + dots + ||mem||^2 + ww sums (all blocks)
        update_phase((const float4*)g_rwbuf[p], bx, tid, sbuf, t);
        grid_sync();
    }
    {
        float uwv[8];
        if (bx < 64) softmax_uw_phase(g_rwbuf[SEQ & 1], bx, SEQ - 1, sbuf, tid, uwv);
    }
    grid_sync();
    readvec_final(bx, NBLK, SEQ - 1, (const float4*)g_rwbuf[SEQ & 1], sbuf, tid);
}

__global__ __launch_bounds__(512) void k_probs(const float* __restrict__ Wf,
                                               const float* __restrict__ bf,
                                               float* __restrict__ out) {
    int g0 = blockIdx.x * 8;
    int tid = threadIdx.x;
    int row = tid >> 6, j = tid & 63;
    __shared__ float sin_[8][1024];
    for (int e = tid; e < 8192; e += 512)
        sin_[e >> 10][e & 1023] = g_outputs[(size_t)(g0 + (e >> 10)) * 1024 + (e & 1023)];
    __syncthreads();
    float acc = bf[j];
    #pragma unroll 8
    for (int k = 0; k < 1024; k++) acc += sin_[row][k] * Wf[k * 64 + j];
    __shared__ float lg[8][64];
    lg[row][j] = acc;
    __syncthreads();
    float mx = -FLT_MAX;
    #pragma unroll
    for (int q = 0; q < 64; q++) mx = fmaxf(mx, lg[row][q]);
    float sum = 0.f;
    #pragma unroll
    for (int q = 0; q < 64; q++) sum += expf(lg[row][q] - mx);
    out[(size_t)(g0 + row) * 64 + j] = expf(acc - mx) / sum;
}

// ---------------- vectorized copy of final states to output ---------------------
__global__ void k_final(float* __restrict__ out) {
    long tid = (long)blockIdx.x * blockDim.x + threadIdx.x;
    long stride = (long)gridDim.x * blockDim.x;
    const long P = (long)BSZ * SEQ * NOUT;
    const long MEMN = (long)BSZ * NN * MM;
    const long RWN = (long)BSZ * RHEAD * NN;
    float* pm = out + P;
    float* pr = pm + MEMN;
    float* pu = pr + RWN;
    const float4* rwfin4 = (const float4*)g_rwbuf[SEQ & 1];
    const float4* mem4 = (const float4*)g_mem;
    float4* pm4 = (float4*)pm;
    for (long i = tid; i < MEMN / 4; i += stride) pm4[i] = mem4[i];
    for (long i = tid; i < (long)BSZ*NN; i += stride) {
        long b = i >> 12, n = i & 4095;
        float4 v = rwfin4[i];
        float* rp = pr + ((b << 2) << 12) + n;
        rp[0]      = v.x;
        rp[NN]     = v.y;
        rp[2 * NN] = v.z;
        rp[3 * NN] = v.w;
    }
    const float4* uw4 = (const float4*)g_uw;
    float4* pu4 = (float4*)pu;
    for (long i = tid; i < (long)BSZ*NN/4; i += stride) pu4[i] = uw4[i];
}

extern "C" void kernel_launch(void* const* d_in, const int* in_sizes, int n_in,
                              void* d_out, int out_size) {
    const float* x     = (const float*)d_in[0];
    const float* y     = (const float*)d_in[1];
    const float* mem   = (const float*)d_in[2];
    const float* rw    = (const float*)d_in[3];
    const float* uw    = (const float*)d_in[4];
    const float* Wl    = (const float*)d_in[5];
    const float* bl    = (const float*)d_in[6];
    const float* Wm    = (const float*)d_in[7];
    const float* bm    = (const float*)d_in[8];
    const float* Wf    = (const float*)d_in[9];
    const float* bf    = (const float*)d_in[10];
    const float* alpha = (const float*)d_in[11];
    float* out = (float*)d_out;

    k_init<<<4096, 256>>>(mem, rw, uw, alpha);
    k_persist<<<NBLK, TPB>>>(x, y, Wl, bl, Wm, bm);
    k_probs<<<1024, 512>>>(Wf, bf, out);

    long total = 524288L + 33554432L + 1048576L + 262144L;
    if ((long)out_size >= total) {
        k_final<<<8192, 256>>>(out);
    }
}

// round 16
// speedup vs baseline: 1.0340x; 1.0130x over previous
#include <cuda_runtime.h>
#include <math.h>
#include <float.h>

#define BSZ   64
#define SEQ   128
#define INP   256
#define HH    512
#define NN    4096
#define MM    128
#define RHEAD 4
#define NOUT  64
#define GAMMA 0.95f
#define KTOT  769
#define NBLK  148
#define TPB   512
#define NROWS (BSZ*NN)
#define RPW   111

typedef unsigned long long ull;

__device__ __align__(16) float g_mem[(size_t)BSZ*NN*MM];
__device__ __align__(16) float g_rwbuf[2][BSZ*RHEAD*NN];
__device__ __align__(16) float g_uw[BSZ*NN];
__device__ float g_wws[BSZ*NN];
__device__ __align__(16) float g_dots[BSZ*RHEAD*NN];
__device__ float g_query[BSZ*HH];
__device__ float g_hid[2][BSZ*HH];
__device__ float g_cell[BSZ*HH];
__device__ float g_outputs[(size_t)BSZ*SEQ*1024];
__device__ float g_alpha_s[BSZ*RHEAD];
__device__ int   g_idx[BSZ*RHEAD];
__device__ float g_q2a[2];
__device__ float g_m2a[2];
__device__ int   g_gcnt[2];
__device__ __align__(128) unsigned g_bar_cnt = 0;
__device__ __align__(128) unsigned g_bar_gen = 0;

// ---------------- packed f32x2 helpers (per-lane IEEE ops, bit-identical) -----
__device__ __forceinline__ ull pk2(float a, float b) {
    ull r; asm("mov.b64 %0, {%1,%2};" : "=l"(r) : "f"(a), "f"(b)); return r;
}
__device__ __forceinline__ void upk2(ull p, float& a, float& b) {
    asm("mov.b64 {%0,%1}, %2;" : "=f"(a), "=f"(b) : "l"(p));
}
__device__ __forceinline__ ull fma2_(ull a, ull b, ull c) {
    ull d; asm("fma.rn.f32x2 %0, %1, %2, %3;" : "=l"(d) : "l"(a), "l"(b), "l"(c)); return d;
}
__device__ __forceinline__ ull mul2_(ull a, ull b) {
    ull d; asm("mul.rn.f32x2 %0, %1, %2;" : "=l"(d) : "l"(a), "l"(b)); return d;
}
__device__ __forceinline__ ull add2_(ull a, ull b) {
    ull d; asm("add.rn.f32x2 %0, %1, %2;" : "=l"(d) : "l"(a), "l"(b)); return d;
}

struct UCtx {
    float4 ql0, ql1, ql2, ql3;
    ull q0xy, q0zw, q1xy, q1zw, q2xy, q2zw, q3xy, q3zw;
    float as0, as1, as2, as3, wc0, wc1, wc2, wc3;
    int ix0, ix1, ix2, ix3;
};
struct UAcc {
    ull rv0xy, rv0zw, rv1xy, rv1zw, rv2xy, rv2zw, rv3xy, rv3zw;
    ull m2a, m2b;
};

__device__ __forceinline__ void grid_sync() {
    __syncthreads();
    if (threadIdx.x == 0) {
        unsigned gen;
        asm volatile("ld.acquire.gpu.u32 %0, [%1];" : "=r"(gen) : "l"(&g_bar_gen));
        unsigned prev;
        asm volatile("atom.acq_rel.gpu.global.add.u32 %0, [%1], %2;"
                     : "=r"(prev) : "l"(&g_bar_cnt), "r"(1u) : "memory");
        if (prev == (unsigned)gridDim.x - 1u) {
            asm volatile("st.relaxed.gpu.u32 [%0], %1;" :: "l"(&g_bar_cnt), "r"(0u) : "memory");
            asm volatile("red.release.gpu.global.add.u32 [%0], %1;" :: "l"(&g_bar_gen), "r"(1u) : "memory");
        } else {
            unsigned cur;
            do {
                asm volatile("ld.acquire.gpu.u32 %0, [%1];" : "=r"(cur) : "l"(&g_bar_gen));
            } while (cur == gen);
        }
    }
    __syncthreads();
}

// ---------------- init: vectorized copies into scratch --------------------------
__global__ void k_init(const float* __restrict__ mem_in,
                       const float* __restrict__ rw_in,
                       const float* __restrict__ uw_in,
                       const float* __restrict__ alpha) {
    long tid = (long)blockIdx.x * blockDim.x + threadIdx.x;
    long stride = (long)gridDim.x * blockDim.x;
    const long MEM4 = (long)BSZ*NN*MM/4;
    const float4* src4 = (const float4*)mem_in;
    float4* dst4 = (float4*)g_mem;
    for (long i = tid; i < MEM4; i += stride) dst4[i] = src4[i];
    float4* rwi = (float4*)g_rwbuf[0];
    for (long i = tid; i < (long)BSZ*NN; i += stride) {
        long b = i >> 12, n = i & 4095;
        const float* rp = rw_in + ((b << 2) << 12) + n;
        float4 v;
        v.x = rp[0];
        v.y = rp[NN];
        v.z = rp[2 * NN];
        v.w = rp[3 * NN];
        rwi[i] = v;
    }
    const long UW4 = (long)BSZ*NN/4;
    const float4* us4 = (const float4*)uw_in;
    float4* ud4 = (float4*)g_uw;
    for (long i = tid; i < UW4; i += stride) ud4[i] = us4[i];
    if (tid < BSZ*RHEAD) g_alpha_s[tid] = 1.0f / (1.0f + expf(-alpha[tid]));
}

__device__ void gemm_gates(const float* __restrict__ x, const float* __restrict__ y,
                           const float* __restrict__ Wl, const float* __restrict__ bl,
                           int t, float* sbuf, int tid, int jblk) {
    float* As = sbuf;
    float* Bs = sbuf + 2112;
    float* Ps = sbuf + 3136;
    const int j0 = jblk * 8;
    const int row = tid >> 3;
    const int cg  = tid & 7;
    const float* hprev = g_hid[(t & 1) ^ 1];

    float acc[4] = {0.f, 0.f, 0.f, 0.f};

    for (int kb = 0; kb < KTOT; kb += 32) {
        #pragma unroll
        for (int i = 0; i < 4; i++) {
            int e = tid + i * 512;
            int r = e >> 5, k = e & 31;
            int kg = kb + k;
            float v = 0.f;
            if (kg < INP) v = x[(r * SEQ + t) * INP + kg];
            else if (kg == INP) { if (t > 0) v = y[r * SEQ + t - 1]; }
            else if (kg < KTOT) { if (t > 0) v = hprev[r * HH + kg - INP - 1]; }
            As[r * 33 + k] = v;
        }
        #pragma unroll
        for (int i = 0; i < 2; i++) {
            int e = tid + i * 512;
            int k = e >> 5, c = e & 31;
            int kg = kb + k;
            float v = 0.f;
            if (kg < KTOT) {
                int g = c >> 3, jj = c & 7;
                v = Wl[kg * (4 * HH) + g * HH + j0 + jj];
            }
            Bs[k * 32 + c] = v;
        }
        __syncthreads();
        #pragma unroll
        for (int k = 0; k < 32; k++) {
            float a = As[row * 33 + k];
            float4 bv = *(const float4*)&Bs[k * 32 + cg * 4];
            acc[0] += a * bv.x; acc[1] += a * bv.y; acc[2] += a * bv.z; acc[3] += a * bv.w;
        }
        __syncthreads();
    }
    #pragma unroll
    for (int i = 0; i < 4; i++) Ps[row * 32 + cg * 4 + i] = acc[i];
    __syncthreads();

    float* hcur = g_hid[t & 1];
    {
        int b = tid >> 3, jj = tid & 7;
        int j = j0 + jj;
        float pf = Ps[b * 32 +  0 + jj] + bl[0 * HH + j];
        float pi = Ps[b * 32 +  8 + jj] + bl[1 * HH + j];
        float po = Ps[b * 32 + 16 + jj] + bl[2 * HH + j];
        float pu = Ps[b * 32 + 24 + jj] + bl[3 * HH + j];
        float f  = 1.f / (1.f + expf(-pf));
        float ig = 1.f / (1.f + expf(-pi));
        float o  = 1.f / (1.f + expf(-po));
        float uu = tanhf(pu);
        float cprev = (t > 0) ? g_cell[b * HH + j] : 0.f;
        float c = f * cprev + ig * uu;
        float h = o * tanhf(c);
        g_cell[b * HH + j] = c;
        hcur[b * HH + j] = h;
        g_outputs[((size_t)b * SEQ + t) * 1024 + j] = h;
    }
}

__device__ void query_phase(int b, int t, const float* __restrict__ Wm,
                            const float* __restrict__ bm, float* sbuf, int tid) {
    const float* h = g_hid[t & 1] + b * HH;
    sbuf[tid] = h[tid];
    __syncthreads();
    float a0 = 0.f, a1 = 0.f, a2 = 0.f, a3 = 0.f;
    #pragma unroll 4
    for (int k = 0; k < HH; k += 4) {
        a0 += sbuf[k]     * Wm[(k)     * HH + tid];
        a1 += sbuf[k + 1] * Wm[(k + 1) * HH + tid];
        a2 += sbuf[k + 2] * Wm[(k + 2) * HH + tid];
        a3 += sbuf[k + 3] * Wm[(k + 3) * HH + tid];
    }
    float qv = a0 + a1 + a2 + a3 + bm[tid];
    g_query[b * HH + tid] = qv;
    float* red = sbuf + 1024;
    red[tid] = qv * qv;
    __syncthreads();
    for (int s = 256; s > 0; s >>= 1) {
        if (tid < s) red[tid] += red[tid + s];
        __syncthreads();
    }
    if (tid == 0) atomicAdd(&g_q2a[t & 1], red[0]);
}

__device__ void idx_phase(int b, float* sbuf, int tid) {
    float v[8]; int nn[8];
    #pragma unroll
    for (int i = 0; i < 8; i++) { int n = tid + i * 512; v[i] = g_uw[b * NN + n]; nn[i] = n; }
    float* sval = sbuf;
    int*   sidx = (int*)(sbuf + 512);
    for (int sel = 0; sel < 4; sel++) {
        float bv = FLT_MAX; int bn = 0x7fffffff;
        #pragma unroll
        for (int i = 0; i < 8; i++)
            if (v[i] < bv || (v[i] == bv && nn[i] < bn)) { bv = v[i]; bn = nn[i]; }
        sval[tid] = bv; sidx[tid] = bn;
        __syncthreads();
        for (int s = 256; s > 0; s >>= 1) {
            if (tid < s) {
                float ov = sval[tid + s]; int on = sidx[tid + s];
                if (ov < sval[tid] || (ov == sval[tid] && on < sidx[tid])) {
                    sval[tid] = ov; sidx[tid] = on;
                }
            }
            __syncthreads();
        }
        int win = sidx[0];
        if (tid == 0) g_idx[b * 4 + sel] = win;
        __syncthreads();
        #pragma unroll
        for (int i = 0; i < 8; i++) if (nn[i] == win) v[i] = FLT_MAX;
    }
}

// ---------------- per-row fused body ---------------------------------------------
__device__ __forceinline__ void urow(int row, float4 v, float4 a,
                                     const UCtx& C, UAcc& A, int lane) {
    ull vxy = pk2(v.x, v.y), vzw = pk2(v.z, v.w);
    ull t;
    t = pk2(a.x, a.x); A.rv0xy = fma2_(t, vxy, A.rv0xy); A.rv0zw = fma2_(t, vzw, A.rv0zw);
    t = pk2(a.y, a.y); A.rv1xy = fma2_(t, vxy, A.rv1xy); A.rv1zw = fma2_(t, vzw, A.rv1zw);
    t = pk2(a.z, a.z); A.rv2xy = fma2_(t, vxy, A.rv2xy); A.rv2zw = fma2_(t, vzw, A.rv2zw);
    t = pk2(a.w, a.w); A.rv3xy = fma2_(t, vxy, A.rv3xy); A.rv3zw = fma2_(t, vzw, A.rv3zw);

    int n = row & 4095;
    float w0 = __fmul_rn(C.as0, a.x); if (C.ix0 == n) w0 = __fadd_rn(w0, C.wc0);
    float w1 = __fmul_rn(C.as1, a.y); if (C.ix1 == n) w1 = __fadd_rn(w1, C.wc1);
    float w2 = __fmul_rn(C.as2, a.z); if (C.ix2 == n) w2 = __fadd_rn(w2, C.wc2);
    float w3 = __fmul_rn(C.as3, a.w); if (C.ix3 == n) w3 = __fadd_rn(w3, C.wc3);
    ull w0p = pk2(w0, w0), w1p = pk2(w1, w1), w2p = pk2(w2, w2), w3p = pk2(w3, w3);
    ull sxy = fma2_(w3p, C.q3xy, fma2_(w2p, C.q2xy, fma2_(w1p, C.q1xy, mul2_(w0p, C.q0xy))));
    ull szw = fma2_(w3p, C.q3zw, fma2_(w2p, C.q2zw, fma2_(w1p, C.q1zw, mul2_(w0p, C.q0zw))));
    vxy = add2_(vxy, sxy);
    vzw = add2_(vzw, szw);
    upk2(vxy, v.x, v.y);
    upk2(vzw, v.z, v.w);
    __stcs((float4*)(g_mem + ((size_t)row << 7) + (lane << 2)), v);

    float d0 = C.ql0.x*v.x + C.ql0.y*v.y + C.ql0.z*v.z + C.ql0.w*v.w;
    float d1 = C.ql1.x*v.x + C.ql1.y*v.y + C.ql1.z*v.z + C.ql1.w*v.w;
    float d2 = C.ql2.x*v.x + C.ql2.y*v.y + C.ql2.z*v.z + C.ql2.w*v.w;
    float d3 = C.ql3.x*v.x + C.ql3.y*v.y + C.ql3.z*v.z + C.ql3.w*v.w;
    d0 += __shfl_xor_sync(0xffffffffu, d0, 16);
    d1 += __shfl_xor_sync(0xffffffffu, d1, 16);
    d2 += __shfl_xor_sync(0xffffffffu, d2, 16);
    d3 += __shfl_xor_sync(0xffffffffu, d3, 16);
    d0 += __shfl_xor_sync(0xffffffffu, d0, 8);
    d1 += __shfl_xor_sync(0xffffffffu, d1, 8);
    d2 += __shfl_xor_sync(0xffffffffu, d2, 8);
    d3 += __shfl_xor_sync(0xffffffffu, d3, 8);
    int g = lane >> 3;
    float dv = (g == 0) ? d0 : (g == 1) ? d1 : (g == 2) ? d2 : d3;
    dv += __shfl_xor_sync(0xffffffffu, dv, 4);
    dv += __shfl_xor_sync(0xffffffffu, dv, 2);
    dv += __shfl_xor_sync(0xffffffffu, dv, 1);
    if ((lane & 7) == 0) g_dots[((size_t)row << 2) + g] = dv;
    if (lane == 0) g_wws[row] = __fadd_rn(__fadd_rn(__fadd_rn(w0, w1), w2), w3);
    A.m2a = fma2_(vxy, vxy, A.m2a);
    A.m2b = fma2_(vzw, vzw, A.m2b);
}

__device__ __forceinline__ void u_group8(int row, const float4* __restrict__ rw4,
                                         const UCtx& C, UAcc& A, int lane) {
    float4 v0 = __ldcs((const float4*)(g_mem + ((size_t)(row    ) << 7) + (lane << 2)));
    float4 v1 = __ldcs((const float4*)(g_mem + ((size_t)(row + 1) << 7) + (lane << 2)));
    float4 v2 = __ldcs((const float4*)(g_mem + ((size_t)(row + 2) << 7) + (lane << 2)));
    float4 v3 = __ldcs((const float4*)(g_mem + ((size_t)(row + 3) << 7) + (lane << 2)));
    float4 v4 = __ldcs((const float4*)(g_mem + ((size_t)(row + 4) << 7) + (lane << 2)));
    float4 v5 = __ldcs((const float4*)(g_mem + ((size_t)(row + 5) << 7) + (lane << 2)));
    float4 v6 = __ldcs((const float4*)(g_mem + ((size_t)(row + 6) << 7) + (lane << 2)));
    float4 v7 = __ldcs((const float4*)(g_mem + ((size_t)(row + 7) << 7) + (lane << 2)));
    urow(row,     v0, rw4[row    ], C, A, lane);
    urow(row + 1, v1, rw4[row + 1], C, A, lane);
    urow(row + 2, v2, rw4[row + 2], C, A, lane);
    urow(row + 3, v3, rw4[row + 3], C, A, lane);
    urow(row + 4, v4, rw4[row + 4], C, A, lane);
    urow(row + 5, v5, rw4[row + 5], C, A, lane);
    urow(row + 6, v6, rw4[row + 6], C, A, lane);
    urow(row + 7, v7, rw4[row + 7], C, A, lane);
}

__device__ void update_phase(const float4* __restrict__ rw4, int bx, int tid,
                             float* sbuf, int t) {
    const int p = t & 1;
    if (bx == 147 && tid == 0) { g_q2a[p ^ 1] = 0.f; g_m2a[p ^ 1] = 0.f; }
    if (bx == 146 && tid == 0) { g_gcnt[p] = 0; }
    int lane = tid & 31;
    int w = bx * 16 + (tid >> 5);
    int r0 = w * RPW;
    int r1 = r0 + RPW; if (r1 > NROWS) r1 = NROWS;
    UAcc A;
    A.m2a = 0ull; A.m2b = 0ull;
    int row = r0;
    while (row < r1) {
        int b = row >> 12;
        int bend = (b + 1) << 12; if (bend > r1) bend = r1;
        UCtx C;
        const float* qb = g_query + b * HH;
        C.ql0 = *(const float4*)(qb + 0 * 128 + lane * 4);
        C.ql1 = *(const float4*)(qb + 1 * 128 + lane * 4);
        C.ql2 = *(const float4*)(qb + 2 * 128 + lane * 4);
        C.ql3 = *(const float4*)(qb + 3 * 128 + lane * 4);
        C.q0xy = pk2(C.ql0.x, C.ql0.y); C.q0zw = pk2(C.ql0.z, C.ql0.w);
        C.q1xy = pk2(C.ql1.x, C.ql1.y); C.q1zw = pk2(C.ql1.z, C.ql1.w);
        C.q2xy = pk2(C.ql2.x, C.ql2.y); C.q2zw = pk2(C.ql2.z, C.ql2.w);
        C.q3xy = pk2(C.ql3.x, C.ql3.y); C.q3zw = pk2(C.ql3.z, C.ql3.w);
        C.as0 = g_alpha_s[b*4+0]; C.as1 = g_alpha_s[b*4+1];
        C.as2 = g_alpha_s[b*4+2]; C.as3 = g_alpha_s[b*4+3];
        C.wc0 = 1.f - C.as0; C.wc1 = 1.f - C.as1; C.wc2 = 1.f - C.as2; C.wc3 = 1.f - C.as3;
        C.ix0 = g_idx[b*4+0]; C.ix1 = g_idx[b*4+1];
        C.ix2 = g_idx[b*4+2]; C.ix3 = g_idx[b*4+3];
        A.rv0xy = 0ull; A.rv0zw = 0ull; A.rv1xy = 0ull; A.rv1zw = 0ull;
        A.rv2xy = 0ull; A.rv2zw = 0ull; A.rv3xy = 0ull; A.rv3zw = 0ull;
        for (; row + 8 <= bend; row += 8)
            u_group8(row, rw4, C, A, lane);
        for (; row < bend; row++) {
            float4 v = __ldcs((const float4*)(g_mem + ((size_t)row << 7) + (lane << 2)));
            urow(row, v, rw4[row], C, A, lane);
        }
        if (t > 0) {
            float4 rv0, rv1, rv2, rv3;
            upk2(A.rv0xy, rv0.x, rv0.y); upk2(A.rv0zw, rv0.z, rv0.w);
            upk2(A.rv1xy, rv1.x, rv1.y); upk2(A.rv1zw, rv1.z, rv1.w);
            upk2(A.rv2xy, rv2.x, rv2.y); upk2(A.rv2zw, rv2.z, rv2.w);
            upk2(A.rv3xy, rv3.x, rv3.y); upk2(A.rv3zw, rv3.z, rv3.w);
            float* dst = g_outputs + ((size_t)b * SEQ + (t - 1)) * 1024 + 512 + lane * 4;
            atomicAdd(dst + 0,       rv0.x); atomicAdd(dst + 1,       rv0.y);
            atomicAdd(dst + 2,       rv0.z); atomicAdd(dst + 3,       rv0.w);
            atomicAdd(dst + 128 + 0, rv1.x); atomicAdd(dst + 128 + 1, rv1.y);
            atomicAdd(dst + 128 + 2, rv1.z); atomicAdd(dst + 128 + 3, rv1.w);
            atomicAdd(dst + 256 + 0, rv2.x); atomicAdd(dst + 256 + 1, rv2.y);
            atomicAdd(dst + 256 + 2, rv2.z); atomicAdd(dst + 256 + 3, rv2.w);
            atomicAdd(dst + 384 + 0, rv3.x); atomicAdd(dst + 384 + 1, rv3.y);
            atomicAdd(dst + 384 + 2, rv3.z); atomicAdd(dst + 384 + 3, rv3.w);
        }
    }
    float m2;
    {
        float ax, ay, bx2, by;
        upk2(A.m2a, ax, ay);
        upk2(A.m2b, bx2, by);
        m2 = (ax + ay) + (bx2 + by);
    }
    #pragma unroll
    for (int o = 16; o > 0; o >>= 1) m2 += __shfl_xor_sync(0xffffffffu, m2, o);
    if (lane == 0) sbuf[tid >> 5] = m2;
    __syncthreads();
    if (tid < 16) {
        float v = sbuf[tid];
        #pragma unroll
        for (int o = 8; o > 0; o >>= 1) v += __shfl_xor_sync(0x0000ffffu, v, o);
        if (tid == 0) atomicAdd(&g_m2a[p], v);
    }
}

__device__ void softmax_uw_phase(float* __restrict__ rwn, int b, int ts,
                                 float* sbuf, int tid) {
    float inv = 1.f / __fmul_rn(sqrtf(g_q2a[ts & 1]), sqrtf(g_m2a[ts & 1]));
    const float4* D = (const float4*)g_dots + (size_t)b * NN;
    float4* rw4 = (float4*)rwn + (size_t)b * NN;
    float4* red = (float4*)sbuf;
    float4 lv[8];
    float4 mx = make_float4(-FLT_MAX, -FLT_MAX, -FLT_MAX, -FLT_MAX);
    #pragma unroll
    for (int i = 0; i < 8; i++) {
        float4 d = D[tid + i * 512];
        lv[i].x = d.x * inv; lv[i].y = d.y * inv; lv[i].z = d.z * inv; lv[i].w = d.w * inv;
        mx.x = fmaxf(mx.x, lv[i].x); mx.y = fmaxf(mx.y, lv[i].y);
        mx.z = fmaxf(mx.z, lv[i].z); mx.w = fmaxf(mx.w, lv[i].w);
    }
    red[tid] = mx; __syncthreads();
    for (int s = 256; s > 0; s >>= 1) {
        if (tid < s) {
            float4 o = red[tid + s];
            red[tid].x = fmaxf(red[tid].x, o.x); red[tid].y = fmaxf(red[tid].y, o.y);
            red[tid].z = fmaxf(red[tid].z, o.z); red[tid].w = fmaxf(red[tid].w, o.w);
        }
        __syncthreads();
    }
    mx = red[0]; __syncthreads();
    float4 sum = make_float4(0.f, 0.f, 0.f, 0.f);
    #pragma unroll
    for (int i = 0; i < 8; i++) {
        lv[i].x = expf(lv[i].x - mx.x); sum.x += lv[i].x;
        lv[i].y = expf(lv[i].y - mx.y); sum.y += lv[i].y;
        lv[i].z = expf(lv[i].z - mx.z); sum.z += lv[i].z;
        lv[i].w = expf(lv[i].w - mx.w); sum.w += lv[i].w;
    }
    red[tid] = sum; __syncthreads();
    for (int s = 256; s > 0; s >>= 1) {
        if (tid < s) {
            float4 o = red[tid + s];
            red[tid].x += o.x; red[tid].y += o.y; red[tid].z += o.z; red[tid].w += o.w;
        }
        __syncthreads();
    }
    float4 isum = red[0];
    isum.x = 1.f / isum.x; isum.y = 1.f / isum.y; isum.z = 1.f / isum.z; isum.w = 1.f / isum.w;
    __syncthreads();
    #pragma unroll
    for (int i = 0; i < 8; i++) {
        int n = tid + i * 512;
        float4 o;
        o.x = lv[i].x * isum.x; o.y = lv[i].y * isum.y;
        o.z = lv[i].z * isum.z; o.w = lv[i].w * isum.w;
        rw4[n] = o;
        float rwsum = __fadd_rn(__fadd_rn(__fadd_rn(o.x, o.y), o.z), o.w);
        int gi = b * NN + n;
        g_uw[gi] = __fadd_rn(__fadd_rn(__fmul_rn(GAMMA, g_uw[gi]), rwsum), g_wws[gi]);
    }
    g_outputs[((size_t)b * SEQ + ts) * 1024 + 512 + tid] = 0.f;
}

__device__ void readvec_final(int ustart, int ustride, int t_out,
                              const float4* __restrict__ rw4,
                              float* sbuf, int tid) {
    int q = tid >> 5, lane = tid & 31;
    for (int u = ustart; u < 512; u += ustride) {
        int b = u >> 3, s = u & 7;
        const float4* rwb = rw4 + (size_t)b * NN;
        float4 a0 = make_float4(0,0,0,0), a1 = a0, a2 = a0, a3 = a0;
        for (int i = 0; i < 32; i += 4) {
            int n0 = s * 512 + i * 16 + q;
            const float4 v0 = __ldcs((const float4*)(g_mem + (((size_t)b * NN + n0)      << 7) + (lane << 2)));
            const float4 v1 = __ldcs((const float4*)(g_mem + (((size_t)b * NN + n0 + 16) << 7) + (lane << 2)));
            const float4 v2 = __ldcs((const float4*)(g_mem + (((size_t)b * NN + n0 + 32) << 7) + (lane << 2)));
            const float4 v3 = __ldcs((const float4*)(g_mem + (((size_t)b * NN + n0 + 48) << 7) + (lane << 2)));
            const float4 w0 = rwb[n0];
            const float4 w1 = rwb[n0 + 16];
            const float4 w2 = rwb[n0 + 32];
            const float4 w3 = rwb[n0 + 48];
            a0.x += w0.x*v0.x; a0.y += w0.x*v0.y; a0.z += w0.x*v0.z; a0.w += w0.x*v0.w;
            a1.x += w0.y*v0.x; a1.y += w0.y*v0.y; a1.z += w0.y*v0.z; a1.w += w0.y*v0.w;
            a2.x += w0.z*v0.x; a2.y += w0.z*v0.y; a2.z += w0.z*v0.z; a2.w += w0.z*v0.w;
            a3.x += w0.w*v0.x; a3.y += w0.w*v0.y; a3.z += w0.w*v0.z; a3.w += w0.w*v0.w;
            a0.x += w1.x*v1.x; a0.y += w1.x*v1.y; a0.z += w1.x*v1.z; a0.w += w1.x*v1.w;
            a1.x += w1.y*v1.x; a1.y += w1.y*v1.y; a1.z += w1.y*v1.z; a1.w += w1.y*v1.w;
            a2.x += w1.z*v1.x; a2.y += w1.z*v1.y; a2.z += w1.z*v1.z; a2.w += w1.z*v1.w;
            a3.x += w1.w*v1.x; a3.y += w1.w*v1.y; a3.z += w1.w*v1.z; a3.w += w1.w*v1.w;
            a0.x += w2.x*v2.x; a0.y += w2.x*v2.y; a0.z += w2.x*v2.z; a0.w += w2.x*v2.w;
            a1.x += w2.y*v2.x; a1.y += w2.y*v2.y; a1.z += w2.y*v2.z; a1.w += w2.y*v2.w;
            a2.x += w2.z*v2.x; a2.y += w2.z*v2.y; a2.z += w2.z*v2.z; a2.w += w2.z*v2.w;
            a3.x += w2.w*v2.x; a3.y += w2.w*v2.y; a3.z += w2.w*v2.z; a3.w += w2.w*v2.w;
            a0.x += w3.x*v3.x; a0.y += w3.x*v3.y; a0.z += w3.x*v3.z; a0.w += w3.x*v3.w;
            a1.x += w3.y*v3.x; a1.y += w3.y*v3.y; a1.z += w3.y*v3.z; a1.w += w3.y*v3.w;
            a2.x += w3.z*v3.x; a2.y += w3.z*v3.y; a2.z += w3.z*v3.z; a2.w += w3.z*v3.w;
            a3.x += w3.w*v3.x; a3.y += w3.w*v3.y; a3.z += w3.w*v3.z; a3.w += w3.w*v3.w;
        }
        ((float4*)sbuf)[(q * 4 + 0) * 32 + lane] = a0;
        ((float4*)sbuf)[(q * 4 + 1) * 32 + lane] = a1;
        ((float4*)sbuf)[(q * 4 + 2) * 32 + lane] = a2;
        ((float4*)sbuf)[(q * 4 + 3) * 32 + lane] = a3;
        __syncthreads();
        {
            int r = tid >> 7, m = tid & 127;
            float vsum = 0.f;
            #pragma unroll
            for (int qq = 0; qq < 16; qq++) vsum += sbuf[(qq * 4 + r) * 128 + m];
            atomicAdd(&g_outputs[((size_t)b * SEQ + t_out) * 1024 + 512 + tid], vsum);
        }
        __syncthreads();
    }
}

__global__ __launch_bounds__(TPB, 1) void k_persist(
    const float* __restrict__ x, const float* __restrict__ y,
    const float* __restrict__ Wl, const float* __restrict__ bl,
    const float* __restrict__ Wm, const float* __restrict__ bm)
{
    __shared__ __align__(16) float sbuf[8448];
    const int tid = threadIdx.x;
    const int bx  = blockIdx.x;

    for (int t = 0; t < SEQ; t++) {
        const int p = t & 1;
        // merged prelude: [0..63] softmax+uw(t-1) -> idx(t); [64..127] gemm(t) -> query(t)
        if (bx < 64) {
            if (t > 0) {
                softmax_uw_phase(g_rwbuf[p], bx, t - 1, sbuf, tid);
                __syncthreads();
            }
            idx_phase(bx, sbuf, tid);
        } else if (bx < 128) {
            gemm_gates(x, y, Wl, bl, t, sbuf, tid, bx - 64);
            __syncthreads();
            if (tid == 0) {
                int prev;
                asm volatile("atom.acq_rel.gpu.global.add.u32 %0, [%1], %2;"
                             : "=r"(prev) : "l"(&g_gcnt[p]), "r"(1u) : "memory");
                int v;
                do { asm volatile("ld.acquire.gpu.u32 %0, [%1];" : "=r"(v) : "l"(&g_gcnt[p])); }
                while (v < 64);
            }
            __syncthreads();
            query_phase(bx - 64, t, Wm, bm, sbuf, tid);
        }
        grid_sync();
        // update(t) + readvec(t-1) + dots + ||mem||^2 + ww sums (all blocks)
        update_phase((const float4*)g_rwbuf[p], bx, tid, sbuf, t);
        grid_sync();
    }
    if (bx < 64) softmax_uw_phase(g_rwbuf[SEQ & 1], bx, SEQ - 1, sbuf, tid);
    grid_sync();
    readvec_final(bx, NBLK, SEQ - 1, (const float4*)g_rwbuf[SEQ & 1], sbuf, tid);
}

__global__ __launch_bounds__(512) void k_probs(const float* __restrict__ Wf,
                                               const float* __restrict__ bf,
                                               float* __restrict__ out) {
    int g0 = blockIdx.x * 8;
    int tid = threadIdx.x;
    int row = tid >> 6, j = tid & 63;
    __shared__ float sin_[8][1024];
    for (int e = tid; e < 8192; e += 512)
        sin_[e >> 10][e & 1023] = g_outputs[(size_t)(g0 + (e >> 10)) * 1024 + (e & 1023)];
    __syncthreads();
    float acc = bf[j];
    #pragma unroll 8
    for (int k = 0; k < 1024; k++) acc += sin_[row][k] * Wf[k * 64 + j];
    __shared__ float lg[8][64];
    lg[row][j] = acc;
    __syncthreads();
    float mx = -FLT_MAX;
    #pragma unroll
    for (int q = 0; q < 64; q++) mx = fmaxf(mx, lg[row][q]);
    float sum = 0.f;
    #pragma unroll
    for (int q = 0; q < 64; q++) sum += expf(lg[row][q] - mx);
    out[(size_t)(g0 + row) * 64 + j] = expf(acc - mx) / sum;
}

// ---------------- vectorized copy of final states to output ---------------------
__global__ void k_final(float* __restrict__ out) {
    long tid = (long)blockIdx.x * blockDim.x + threadIdx.x;
    long stride = (long)gridDim.x * blockDim.x;
    const long P = (long)BSZ * SEQ * NOUT;
    const long MEMN = (long)BSZ * NN * MM;
    const long RWN = (long)BSZ * RHEAD * NN;
    float* pm = out + P;
    float* pr = pm + MEMN;
    float* pu = pr + RWN;
    const float4* rwfin4 = (const float4*)g_rwbuf[SEQ & 1];
    const float4* mem4 = (const float4*)g_mem;
    float4* pm4 = (float4*)pm;
    for (long i = tid; i < MEMN / 4; i += stride) pm4[i] = mem4[i];
    for (long i = tid; i < (long)BSZ*NN; i += stride) {
        long b = i >> 12, n = i & 4095;
        float4 v = rwfin4[i];
        float* rp = pr + ((b << 2) << 12) + n;
        rp[0]      = v.x;
        rp[NN]     = v.y;
        rp[2 * NN] = v.z;
        rp[3 * NN] = v.w;
    }
    const float4* uw4 = (const float4*)g_uw;
    float4* pu4 = (float4*)pu;
    for (long i = tid; i < (long)BSZ*NN/4; i += stride) pu4[i] = uw4[i];
}

extern "C" void kernel_launch(void* const* d_in, const int* in_sizes, int n_in,
                              void* d_out, int out_size) {
    const float* x     = (const float*)d_in[0];
    const float* y     = (const float*)d_in[1];
    const float* mem   = (const float*)d_in[2];
    const float* rw    = (const float*)d_in[3];
    const float* uw    = (const float*)d_in[4];
    const float* Wl    = (const float*)d_in[5];
    const float* bl    = (const float*)d_in[6];
    const float* Wm    = (const float*)d_in[7];
    const float* bm    = (const float*)d_in[8];
    const float* Wf    = (const float*)d_in[9];
    const float* bf    = (const float*)d_in[10];
    const float* alpha = (const float*)d_in[11];
    float* out = (float*)d_out;

    k_init<<<4096, 256>>>(mem, rw, uw, alpha);
    k_persist<<<NBLK, TPB>>>(x, y, Wl, bl, Wm, bm);
    k_probs<<<1024, 512>>>(Wf, bf, out);

    long total = 524288L + 33554432L + 1048576L + 262144L;
    if ((long)out_size >= total) {
        k_final<<<8192, 256>>>(out);
    }
}

// round 17
// speedup vs baseline: 1.0557x; 1.0209x over previous
#include <cuda_runtime.h>
#include <math.h>
#include <float.h>

#define BSZ   64
#define SEQ   128
#define INP   256
#define HH    512
#define NN    4096
#define MM    128
#define RHEAD 4
#define NOUT  64
#define GAMMA 0.95f
#define KTOT  769
#define NBLK  148
#define TPB   512
#define NROWS (BSZ*NN)
#define RPW   111

typedef unsigned long long ull;

__device__ __align__(16) float g_mem[(size_t)BSZ*NN*MM];
__device__ __align__(16) float g_rwbuf[2][BSZ*RHEAD*NN];
__device__ __align__(16) float g_uw[BSZ*NN];
__device__ float g_wws[BSZ*NN];
__device__ __align__(16) float g_dots[BSZ*RHEAD*NN];
__device__ float g_query[BSZ*HH];
__device__ float g_hid[2][BSZ*HH];
__device__ float g_cell[BSZ*HH];
__device__ float g_outputs[(size_t)BSZ*SEQ*1024];
__device__ float g_alpha_s[BSZ*RHEAD];
__device__ int   g_idx[BSZ*RHEAD];
__device__ float g_q2a[2];
__device__ float g_m2a[2];
__device__ int   g_gcnt[2];
__device__ __align__(128) unsigned g_bar_cnt = 0;
__device__ __align__(128) unsigned g_bar_gen = 0;

// ---------------- packed f32x2 helpers (per-lane IEEE ops, bit-identical) -----
__device__ __forceinline__ ull pk2(float a, float b) {
    ull r; asm("mov.b64 %0, {%1,%2};" : "=l"(r) : "f"(a), "f"(b)); return r;
}
__device__ __forceinline__ void upk2(ull p, float& a, float& b) {
    asm("mov.b64 {%0,%1}, %2;" : "=f"(a), "=f"(b) : "l"(p));
}
__device__ __forceinline__ ull fma2_(ull a, ull b, ull c) {
    ull d; asm("fma.rn.f32x2 %0, %1, %2, %3;" : "=l"(d) : "l"(a), "l"(b), "l"(c)); return d;
}
__device__ __forceinline__ ull mul2_(ull a, ull b) {
    ull d; asm("mul.rn.f32x2 %0, %1, %2;" : "=l"(d) : "l"(a), "l"(b)); return d;
}
__device__ __forceinline__ ull add2_(ull a, ull b) {
    ull d; asm("add.rn.f32x2 %0, %1, %2;" : "=l"(d) : "l"(a), "l"(b)); return d;
}

struct UCtx {
    float4 ql0, ql1, ql2, ql3;
    ull q0xy, q0zw, q1xy, q1zw, q2xy, q2zw, q3xy, q3zw;
    float as0, as1, as2, as3, wc0, wc1, wc2, wc3;
    int ix0, ix1, ix2, ix3;
};
struct UAcc {
    ull rv0xy, rv0zw, rv1xy, rv1zw, rv2xy, rv2zw, rv3xy, rv3zw;
    ull m2a, m2b;
};

__device__ __forceinline__ void grid_sync() {
    __syncthreads();
    if (threadIdx.x == 0) {
        unsigned gen;
        asm volatile("ld.acquire.gpu.u32 %0, [%1];" : "=r"(gen) : "l"(&g_bar_gen));
        unsigned prev;
        asm volatile("atom.acq_rel.gpu.global.add.u32 %0, [%1], %2;"
                     : "=r"(prev) : "l"(&g_bar_cnt), "r"(1u) : "memory");
        if (prev == (unsigned)gridDim.x - 1u) {
            asm volatile("st.relaxed.gpu.u32 [%0], %1;" :: "l"(&g_bar_cnt), "r"(0u) : "memory");
            asm volatile("red.release.gpu.global.add.u32 [%0], %1;" :: "l"(&g_bar_gen), "r"(1u) : "memory");
        } else {
            unsigned cur;
            do {
                asm volatile("ld.acquire.gpu.u32 %0, [%1];" : "=r"(cur) : "l"(&g_bar_gen));
            } while (cur == gen);
        }
    }
    __syncthreads();
}

// ---------------- init: vectorized copies into scratch --------------------------
__global__ void k_init(const float* __restrict__ mem_in,
                       const float* __restrict__ rw_in,
                       const float* __restrict__ uw_in,
                       const float* __restrict__ alpha) {
    long tid = (long)blockIdx.x * blockDim.x + threadIdx.x;
    long stride = (long)gridDim.x * blockDim.x;
    const long MEM4 = (long)BSZ*NN*MM/4;
    const float4* src4 = (const float4*)mem_in;
    float4* dst4 = (float4*)g_mem;
    for (long i = tid; i < MEM4; i += stride) dst4[i] = src4[i];
    float4* rwi = (float4*)g_rwbuf[0];
    for (long i = tid; i < (long)BSZ*NN; i += stride) {
        long b = i >> 12, n = i & 4095;
        const float* rp = rw_in + ((b << 2) << 12) + n;
        float4 v;
        v.x = rp[0];
        v.y = rp[NN];
        v.z = rp[2 * NN];
        v.w = rp[3 * NN];
        rwi[i] = v;
    }
    const long UW4 = (long)BSZ*NN/4;
    const float4* us4 = (const float4*)uw_in;
    float4* ud4 = (float4*)g_uw;
    for (long i = tid; i < UW4; i += stride) ud4[i] = us4[i];
    if (tid < BSZ*RHEAD) g_alpha_s[tid] = 1.0f / (1.0f + expf(-alpha[tid]));
}

__device__ void gemm_gates(const float* __restrict__ x, const float* __restrict__ y,
                           const float* __restrict__ Wl, const float* __restrict__ bl,
                           int t, float* sbuf, int tid, int jblk) {
    float* As = sbuf;
    float* Bs = sbuf + 2112;
    float* Ps = sbuf + 3136;
    const int j0 = jblk * 8;
    const int row = tid >> 3;
    const int cg  = tid & 7;
    const float* hprev = g_hid[(t & 1) ^ 1];

    float acc[4] = {0.f, 0.f, 0.f, 0.f};

    for (int kb = 0; kb < KTOT; kb += 32) {
        #pragma unroll
        for (int i = 0; i < 4; i++) {
            int e = tid + i * 512;
            int r = e >> 5, k = e & 31;
            int kg = kb + k;
            float v = 0.f;
            if (kg < INP) v = x[(r * SEQ + t) * INP + kg];
            else if (kg == INP) { if (t > 0) v = y[r * SEQ + t - 1]; }
            else if (kg < KTOT) { if (t > 0) v = hprev[r * HH + kg - INP - 1]; }
            As[r * 33 + k] = v;
        }
        #pragma unroll
        for (int i = 0; i < 2; i++) {
            int e = tid + i * 512;
            int k = e >> 5, c = e & 31;
            int kg = kb + k;
            float v = 0.f;
            if (kg < KTOT) {
                int g = c >> 3, jj = c & 7;
                v = Wl[kg * (4 * HH) + g * HH + j0 + jj];
            }
            Bs[k * 32 + c] = v;
        }
        __syncthreads();
        #pragma unroll
        for (int k = 0; k < 32; k++) {
            float a = As[row * 33 + k];
            float4 bv = *(const float4*)&Bs[k * 32 + cg * 4];
            acc[0] += a * bv.x; acc[1] += a * bv.y; acc[2] += a * bv.z; acc[3] += a * bv.w;
        }
        __syncthreads();
    }
    #pragma unroll
    for (int i = 0; i < 4; i++) Ps[row * 32 + cg * 4 + i] = acc[i];
    __syncthreads();

    float* hcur = g_hid[t & 1];
    {
        int b = tid >> 3, jj = tid & 7;
        int j = j0 + jj;
        float pf = Ps[b * 32 +  0 + jj] + bl[0 * HH + j];
        float pi = Ps[b * 32 +  8 + jj] + bl[1 * HH + j];
        float po = Ps[b * 32 + 16 + jj] + bl[2 * HH + j];
        float pu = Ps[b * 32 + 24 + jj] + bl[3 * HH + j];
        float f  = 1.f / (1.f + expf(-pf));
        float ig = 1.f / (1.f + expf(-pi));
        float o  = 1.f / (1.f + expf(-po));
        float uu = tanhf(pu);
        float cprev = (t > 0) ? g_cell[b * HH + j] : 0.f;
        float c = f * cprev + ig * uu;
        float h = o * tanhf(c);
        g_cell[b * HH + j] = c;
        hcur[b * HH + j] = h;
        g_outputs[((size_t)b * SEQ + t) * 1024 + j] = h;
    }
}

__device__ void query_phase(int b, int t, const float* __restrict__ Wm,
                            const float* __restrict__ bm, float* sbuf, int tid) {
    const float* h = g_hid[t & 1] + b * HH;
    sbuf[tid] = h[tid];
    __syncthreads();
    float a0 = 0.f, a1 = 0.f, a2 = 0.f, a3 = 0.f;
    #pragma unroll 4
    for (int k = 0; k < HH; k += 4) {
        a0 += sbuf[k]     * Wm[(k)     * HH + tid];
        a1 += sbuf[k + 1] * Wm[(k + 1) * HH + tid];
        a2 += sbuf[k + 2] * Wm[(k + 2) * HH + tid];
        a3 += sbuf[k + 3] * Wm[(k + 3) * HH + tid];
    }
    float qv = a0 + a1 + a2 + a3 + bm[tid];
    g_query[b * HH + tid] = qv;
    float* red = sbuf + 1024;
    red[tid] = qv * qv;
    __syncthreads();
    for (int s = 256; s > 0; s >>= 1) {
        if (tid < s) red[tid] += red[tid + s];
        __syncthreads();
    }
    if (tid == 0) atomicAdd(&g_q2a[t & 1], red[0]);
}

__device__ void idx_phase(int b, float* sbuf, int tid) {
    float v[8]; int nn[8];
    #pragma unroll
    for (int i = 0; i < 8; i++) { int n = tid + i * 512; v[i] = g_uw[b * NN + n]; nn[i] = n; }
    float* sval = sbuf;
    int*   sidx = (int*)(sbuf + 512);
    for (int sel = 0; sel < 4; sel++) {
        float bv = FLT_MAX; int bn = 0x7fffffff;
        #pragma unroll
        for (int i = 0; i < 8; i++)
            if (v[i] < bv || (v[i] == bv && nn[i] < bn)) { bv = v[i]; bn = nn[i]; }
        sval[tid] = bv; sidx[tid] = bn;
        __syncthreads();
        for (int s = 256; s > 0; s >>= 1) {
            if (tid < s) {
                float ov = sval[tid + s]; int on = sidx[tid + s];
                if (ov < sval[tid] || (ov == sval[tid] && on < sidx[tid])) {
                    sval[tid] = ov; sidx[tid] = on;
                }
            }
            __syncthreads();
        }
        int win = sidx[0];
        if (tid == 0) g_idx[b * 4 + sel] = win;
        __syncthreads();
        #pragma unroll
        for (int i = 0; i < 8; i++) if (nn[i] == win) v[i] = FLT_MAX;
    }
}

// ---------------- per-row fused body ---------------------------------------------
__device__ __forceinline__ void urow(int row, float4 v, float4 a,
                                     const UCtx& C, UAcc& A, int lane) {
    ull vxy = pk2(v.x, v.y), vzw = pk2(v.z, v.w);
    ull t;
    t = pk2(a.x, a.x); A.rv0xy = fma2_(t, vxy, A.rv0xy); A.rv0zw = fma2_(t, vzw, A.rv0zw);
    t = pk2(a.y, a.y); A.rv1xy = fma2_(t, vxy, A.rv1xy); A.rv1zw = fma2_(t, vzw, A.rv1zw);
    t = pk2(a.z, a.z); A.rv2xy = fma2_(t, vxy, A.rv2xy); A.rv2zw = fma2_(t, vzw, A.rv2zw);
    t = pk2(a.w, a.w); A.rv3xy = fma2_(t, vxy, A.rv3xy); A.rv3zw = fma2_(t, vzw, A.rv3zw);

    int n = row & 4095;
    float w0 = __fmul_rn(C.as0, a.x); if (C.ix0 == n) w0 = __fadd_rn(w0, C.wc0);
    float w1 = __fmul_rn(C.as1, a.y); if (C.ix1 == n) w1 = __fadd_rn(w1, C.wc1);
    float w2 = __fmul_rn(C.as2, a.z); if (C.ix2 == n) w2 = __fadd_rn(w2, C.wc2);
    float w3 = __fmul_rn(C.as3, a.w); if (C.ix3 == n) w3 = __fadd_rn(w3, C.wc3);
    ull w0p = pk2(w0, w0), w1p = pk2(w1, w1), w2p = pk2(w2, w2), w3p = pk2(w3, w3);
    ull sxy = fma2_(w3p, C.q3xy, fma2_(w2p, C.q2xy, fma2_(w1p, C.q1xy, mul2_(w0p, C.q0xy))));
    ull szw = fma2_(w3p, C.q3zw, fma2_(w2p, C.q2zw, fma2_(w1p, C.q1zw, mul2_(w0p, C.q0zw))));
    vxy = add2_(vxy, sxy);
    vzw = add2_(vzw, szw);
    upk2(vxy, v.x, v.y);
    upk2(vzw, v.z, v.w);
    __stcs((float4*)(g_mem + ((size_t)row << 7) + (lane << 2)), v);

    float d0 = C.ql0.x*v.x + C.ql0.y*v.y + C.ql0.z*v.z + C.ql0.w*v.w;
    float d1 = C.ql1.x*v.x + C.ql1.y*v.y + C.ql1.z*v.z + C.ql1.w*v.w;
    float d2 = C.ql2.x*v.x + C.ql2.y*v.y + C.ql2.z*v.z + C.ql2.w*v.w;
    float d3 = C.ql3.x*v.x + C.ql3.y*v.y + C.ql3.z*v.z + C.ql3.w*v.w;
    d0 += __shfl_xor_sync(0xffffffffu, d0, 16);
    d1 += __shfl_xor_sync(0xffffffffu, d1, 16);
    d2 += __shfl_xor_sync(0xffffffffu, d2, 16);
    d3 += __shfl_xor_sync(0xffffffffu, d3, 16);
    d0 += __shfl_xor_sync(0xffffffffu, d0, 8);
    d1 += __shfl_xor_sync(0xffffffffu, d1, 8);
    d2 += __shfl_xor_sync(0xffffffffu, d2, 8);
    d3 += __shfl_xor_sync(0xffffffffu, d3, 8);
    int g = lane >> 3;
    float dv = (g == 0) ? d0 : (g == 1) ? d1 : (g == 2) ? d2 : d3;
    dv += __shfl_xor_sync(0xffffffffu, dv, 4);
    dv += __shfl_xor_sync(0xffffffffu, dv, 2);
    dv += __shfl_xor_sync(0xffffffffu, dv, 1);
    if ((lane & 7) == 0) g_dots[((size_t)row << 2) + g] = dv;
    if (lane == 0) g_wws[row] = __fadd_rn(__fadd_rn(__fadd_rn(w0, w1), w2), w3);
    A.m2a = fma2_(vxy, vxy, A.m2a);
    A.m2b = fma2_(vzw, vzw, A.m2b);
}

__device__ __forceinline__ void u_group8(int row, const float4* __restrict__ rw4,
                                         const UCtx& C, UAcc& A, int lane) {
    // all 16 independent loads (8 mem rows + 8 rw broadcasts) issued up front
    float4 v0 = __ldcs((const float4*)(g_mem + ((size_t)(row    ) << 7) + (lane << 2)));
    float4 v1 = __ldcs((const float4*)(g_mem + ((size_t)(row + 1) << 7) + (lane << 2)));
    float4 v2 = __ldcs((const float4*)(g_mem + ((size_t)(row + 2) << 7) + (lane << 2)));
    float4 v3 = __ldcs((const float4*)(g_mem + ((size_t)(row + 3) << 7) + (lane << 2)));
    float4 v4 = __ldcs((const float4*)(g_mem + ((size_t)(row + 4) << 7) + (lane << 2)));
    float4 v5 = __ldcs((const float4*)(g_mem + ((size_t)(row + 5) << 7) + (lane << 2)));
    float4 v6 = __ldcs((const float4*)(g_mem + ((size_t)(row + 6) << 7) + (lane << 2)));
    float4 v7 = __ldcs((const float4*)(g_mem + ((size_t)(row + 7) << 7) + (lane << 2)));
    float4 a0 = rw4[row    ];
    float4 a1 = rw4[row + 1];
    float4 a2 = rw4[row + 2];
    float4 a3 = rw4[row + 3];
    float4 a4 = rw4[row + 4];
    float4 a5 = rw4[row + 5];
    float4 a6 = rw4[row + 6];
    float4 a7 = rw4[row + 7];
    urow(row,     v0, a0, C, A, lane);
    urow(row + 1, v1, a1, C, A, lane);
    urow(row + 2, v2, a2, C, A, lane);
    urow(row + 3, v3, a3, C, A, lane);
    urow(row + 4, v4, a4, C, A, lane);
    urow(row + 5, v5, a5, C, A, lane);
    urow(row + 6, v6, a6, C, A, lane);
    urow(row + 7, v7, a7, C, A, lane);
}

__device__ void update_phase(const float4* __restrict__ rw4, int bx, int tid,
                             float* sbuf, int t) {
    const int p = t & 1;
    if (bx == 147 && tid == 0) { g_q2a[p ^ 1] = 0.f; g_m2a[p ^ 1] = 0.f; }
    if (bx == 146 && tid == 0) { g_gcnt[p] = 0; }
    int lane = tid & 31;
    int w = bx * 16 + (tid >> 5);
    int r0 = w * RPW;
    int r1 = r0 + RPW; if (r1 > NROWS) r1 = NROWS;
    UAcc A;
    A.m2a = 0ull; A.m2b = 0ull;
    int row = r0;
    while (row < r1) {
        int b = row >> 12;
        int bend = (b + 1) << 12; if (bend > r1) bend = r1;
        UCtx C;
        const float* qb = g_query + b * HH;
        C.ql0 = *(const float4*)(qb + 0 * 128 + lane * 4);
        C.ql1 = *(const float4*)(qb + 1 * 128 + lane * 4);
        C.ql2 = *(const float4*)(qb + 2 * 128 + lane * 4);
        C.ql3 = *(const float4*)(qb + 3 * 128 + lane * 4);
        C.q0xy = pk2(C.ql0.x, C.ql0.y); C.q0zw = pk2(C.ql0.z, C.ql0.w);
        C.q1xy = pk2(C.ql1.x, C.ql1.y); C.q1zw = pk2(C.ql1.z, C.ql1.w);
        C.q2xy = pk2(C.ql2.x, C.ql2.y); C.q2zw = pk2(C.ql2.z, C.ql2.w);
        C.q3xy = pk2(C.ql3.x, C.ql3.y); C.q3zw = pk2(C.ql3.z, C.ql3.w);
        C.as0 = g_alpha_s[b*4+0]; C.as1 = g_alpha_s[b*4+1];
        C.as2 = g_alpha_s[b*4+2]; C.as3 = g_alpha_s[b*4+3];
        C.wc0 = 1.f - C.as0; C.wc1 = 1.f - C.as1; C.wc2 = 1.f - C.as2; C.wc3 = 1.f - C.as3;
        C.ix0 = g_idx[b*4+0]; C.ix1 = g_idx[b*4+1];
        C.ix2 = g_idx[b*4+2]; C.ix3 = g_idx[b*4+3];
        A.rv0xy = 0ull; A.rv0zw = 0ull; A.rv1xy = 0ull; A.rv1zw = 0ull;
        A.rv2xy = 0ull; A.rv2zw = 0ull; A.rv3xy = 0ull; A.rv3zw = 0ull;
        for (; row + 8 <= bend; row += 8)
            u_group8(row, rw4, C, A, lane);
        for (; row < bend; row++) {
            float4 v = __ldcs((const float4*)(g_mem + ((size_t)row << 7) + (lane << 2)));
            urow(row, v, rw4[row], C, A, lane);
        }
        if (t > 0) {
            float4 rv0, rv1, rv2, rv3;
            upk2(A.rv0xy, rv0.x, rv0.y); upk2(A.rv0zw, rv0.z, rv0.w);
            upk2(A.rv1xy, rv1.x, rv1.y); upk2(A.rv1zw, rv1.z, rv1.w);
            upk2(A.rv2xy, rv2.x, rv2.y); upk2(A.rv2zw, rv2.z, rv2.w);
            upk2(A.rv3xy, rv3.x, rv3.y); upk2(A.rv3zw, rv3.z, rv3.w);
            float* dst = g_outputs + ((size_t)b * SEQ + (t - 1)) * 1024 + 512 + lane * 4;
            atomicAdd(dst + 0,       rv0.x); atomicAdd(dst + 1,       rv0.y);
            atomicAdd(dst + 2,       rv0.z); atomicAdd(dst + 3,       rv0.w);
            atomicAdd(dst + 128 + 0, rv1.x); atomicAdd(dst + 128 + 1, rv1.y);
            atomicAdd(dst + 128 + 2, rv1.z); atomicAdd(dst + 128 + 3, rv1.w);
            atomicAdd(dst + 256 + 0, rv2.x); atomicAdd(dst + 256 + 1, rv2.y);
            atomicAdd(dst + 256 + 2, rv2.z); atomicAdd(dst + 256 + 3, rv2.w);
            atomicAdd(dst + 384 + 0, rv3.x); atomicAdd(dst + 384 + 1, rv3.y);
            atomicAdd(dst + 384 + 2, rv3.z); atomicAdd(dst + 384 + 3, rv3.w);
        }
    }
    float m2;
    {
        float ax, ay, bx2, by;
        upk2(A.m2a, ax, ay);
        upk2(A.m2b, bx2, by);
        m2 = (ax + ay) + (bx2 + by);
    }
    #pragma unroll
    for (int o = 16; o > 0; o >>= 1) m2 += __shfl_xor_sync(0xffffffffu, m2, o);
    if (lane == 0) sbuf[tid >> 5] = m2;
    __syncthreads();
    if (tid < 16) {
        float v = sbuf[tid];
        #pragma unroll
        for (int o = 8; o > 0; o >>= 1) v += __shfl_xor_sync(0x0000ffffu, v, o);
        if (tid == 0) atomicAdd(&g_m2a[p], v);
    }
}

__device__ void softmax_uw_phase(float* __restrict__ rwn, int b, int ts,
                                 float* sbuf, int tid) {
    float inv = 1.f / __fmul_rn(sqrtf(g_q2a[ts & 1]), sqrtf(g_m2a[ts & 1]));
    const float4* D = (const float4*)g_dots + (size_t)b * NN;
    float4* rw4 = (float4*)rwn + (size_t)b * NN;
    float4* red = (float4*)sbuf;
    float4 lv[8];
    float4 mx = make_float4(-FLT_MAX, -FLT_MAX, -FLT_MAX, -FLT_MAX);
    #pragma unroll
    for (int i = 0; i < 8; i++) {
        float4 d = D[tid + i * 512];
        lv[i].x = d.x * inv; lv[i].y = d.y * inv; lv[i].z = d.z * inv; lv[i].w = d.w * inv;
        mx.x = fmaxf(mx.x, lv[i].x); mx.y = fmaxf(mx.y, lv[i].y);
        mx.z = fmaxf(mx.z, lv[i].z); mx.w = fmaxf(mx.w, lv[i].w);
    }
    red[tid] = mx; __syncthreads();
    for (int s = 256; s > 0; s >>= 1) {
        if (tid < s) {
            float4 o = red[tid + s];
            red[tid].x = fmaxf(red[tid].x, o.x); red[tid].y = fmaxf(red[tid].y, o.y);
            red[tid].z = fmaxf(red[tid].z, o.z); red[tid].w = fmaxf(red[tid].w, o.w);
        }
        __syncthreads();
    }
    mx = red[0]; __syncthreads();
    float4 sum = make_float4(0.f, 0.f, 0.f, 0.f);
    #pragma unroll
    for (int i = 0; i < 8; i++) {
        lv[i].x = expf(lv[i].x - mx.x); sum.x += lv[i].x;
        lv[i].y = expf(lv[i].y - mx.y); sum.y += lv[i].y;
        lv[i].z = expf(lv[i].z - mx.z); sum.z += lv[i].z;
        lv[i].w = expf(lv[i].w - mx.w); sum.w += lv[i].w;
    }
    red[tid] = sum; __syncthreads();
    for (int s = 256; s > 0; s >>= 1) {
        if (tid < s) {
            float4 o = red[tid + s];
            red[tid].x += o.x; red[tid].y += o.y; red[tid].z += o.z; red[tid].w += o.w;
        }
        __syncthreads();
    }
    float4 isum = red[0];
    isum.x = 1.f / isum.x; isum.y = 1.f / isum.y; isum.z = 1.f / isum.z; isum.w = 1.f / isum.w;
    __syncthreads();
    #pragma unroll
    for (int i = 0; i < 8; i++) {
        int n = tid + i * 512;
        float4 o;
        o.x = lv[i].x * isum.x; o.y = lv[i].y * isum.y;
        o.z = lv[i].z * isum.z; o.w = lv[i].w * isum.w;
        rw4[n] = o;
        float rwsum = __fadd_rn(__fadd_rn(__fadd_rn(o.x, o.y), o.z), o.w);
        int gi = b * NN + n;
        g_uw[gi] = __fadd_rn(__fadd_rn(__fmul_rn(GAMMA, g_uw[gi]), rwsum), g_wws[gi]);
    }
    g_outputs[((size_t)b * SEQ + ts) * 1024 + 512 + tid] = 0.f;
}

__device__ void readvec_final(int ustart, int ustride, int t_out,
                              const float4* __restrict__ rw4,
                              float* sbuf, int tid) {
    int q = tid >> 5, lane = tid & 31;
    for (int u = ustart; u < 512; u += ustride) {
        int b = u >> 3, s = u & 7;
        const float4* rwb = rw4 + (size_t)b * NN;
        float4 a0 = make_float4(0,0,0,0), a1 = a0, a2 = a0, a3 = a0;
        for (int i = 0; i < 32; i += 4) {
            int n0 = s * 512 + i * 16 + q;
            const float4 v0 = __ldcs((const float4*)(g_mem + (((size_t)b * NN + n0)      << 7) + (lane << 2)));
            const float4 v1 = __ldcs((const float4*)(g_mem + (((size_t)b * NN + n0 + 16) << 7) + (lane << 2)));
            const float4 v2 = __ldcs((const float4*)(g_mem + (((size_t)b * NN + n0 + 32) << 7) + (lane << 2)));
            const float4 v3 = __ldcs((const float4*)(g_mem + (((size_t)b * NN + n0 + 48) << 7) + (lane << 2)));
            const float4 w0 = rwb[n0];
            const float4 w1 = rwb[n0 + 16];
            const float4 w2 = rwb[n0 + 32];
            const float4 w3 = rwb[n0 + 48];
            a0.x += w0.x*v0.x; a0.y += w0.x*v0.y; a0.z += w0.x*v0.z; a0.w += w0.x*v0.w;
            a1.x += w0.y*v0.x; a1.y += w0.y*v0.y; a1.z += w0.y*v0.z; a1.w += w0.y*v0.w;
            a2.x += w0.z*v0.x; a2.y += w0.z*v0.y; a2.z += w0.z*v0.z; a2.w += w0.z*v0.w;
            a3.x += w0.w*v0.x; a3.y += w0.w*v0.y; a3.z += w0.w*v0.z; a3.w += w0.w*v0.w;
            a0.x += w1.x*v1.x; a0.y += w1.x*v1.y; a0.z += w1.x*v1.z; a0.w += w1.x*v1.w;
            a1.x += w1.y*v1.x; a1.y += w1.y*v1.y; a1.z += w1.y*v1.z; a1.w += w1.y*v1.w;
            a2.x += w1.z*v1.x; a2.y += w1.z*v1.y; a2.z += w1.z*v1.z; a2.w += w1.z*v1.w;
            a3.x += w1.w*v1.x; a3.y += w1.w*v1.y; a3.z += w1.w*v1.z; a3.w += w1.w*v1.w;
            a0.x += w2.x*v2.x; a0.y += w2.x*v2.y; a0.z += w2.x*v2.z; a0.w += w2.x*v2.w;
            a1.x += w2.y*v2.x; a1.y += w2.y*v2.y; a1.z += w2.y*v2.z; a1.w += w2.y*v2.w;
            a2.x += w2.z*v2.x; a2.y += w2.z*v2.y; a2.z += w2.z*v2.z; a2.w += w2.z*v2.w;
            a3.x += w2.w*v2.x; a3.y += w2.w*v2.y; a3.z += w2.w*v2.z; a3.w += w2.w*v2.w;
            a0.x += w3.x*v3.x; a0.y += w3.x*v3.y; a0.z += w3.x*v3.z; a0.w += w3.x*v3.w;
            a1.x += w3.y*v3.x; a1.y += w3.y*v3.y; a1.z += w3.y*v3.z; a1.w += w3.y*v3.w;
            a2.x += w3.z*v3.x; a2.y += w3.z*v3.y; a2.z += w3.z*v3.z; a2.w += w3.z*v3.w;
            a3.x += w3.w*v3.x; a3.y += w3.w*v3.y; a3.z += w3.w*v3.z; a3.w += w3.w*v3.w;
        }
        ((float4*)sbuf)[(q * 4 + 0) * 32 + lane] = a0;
        ((float4*)sbuf)[(q * 4 + 1) * 32 + lane] = a1;
        ((float4*)sbuf)[(q * 4 + 2) * 32 + lane] = a2;
        ((float4*)sbuf)[(q * 4 + 3) * 32 + lane] = a3;
        __syncthreads();
        {
            int r = tid >> 7, m = tid & 127;
            float vsum = 0.f;
            #pragma unroll
            for (int qq = 0; qq < 16; qq++) vsum += sbuf[(qq * 4 + r) * 128 + m];
            atomicAdd(&g_outputs[((size_t)b * SEQ + t_out) * 1024 + 512 + tid], vsum);
        }
        __syncthreads();
    }
}

__global__ __launch_bounds__(TPB, 1) void k_persist(
    const float* __restrict__ x, const float* __restrict__ y,
    const float* __restrict__ Wl, const float* __restrict__ bl,
    const float* __restrict__ Wm, const float* __restrict__ bm)
{
    __shared__ __align__(16) float sbuf[8448];
    const int tid = threadIdx.x;
    const int bx  = blockIdx.x;

    for (int t = 0; t < SEQ; t++) {
        const int p = t & 1;
        // merged prelude: [0..63] softmax+uw(t-1) -> idx(t); [64..127] gemm(t) -> query(t)
        if (bx < 64) {
            if (t > 0) {
                softmax_uw_phase(g_rwbuf[p], bx, t - 1, sbuf, tid);
                __syncthreads();
            }
            idx_phase(bx, sbuf, tid);
        } else if (bx < 128) {
            gemm_gates(x, y, Wl, bl, t, sbuf, tid, bx - 64);
            __syncthreads();
            if (tid == 0) {
                int prev;
                asm volatile("atom.acq_rel.gpu.global.add.u32 %0, [%1], %2;"
                             : "=r"(prev) : "l"(&g_gcnt[p]), "r"(1u) : "memory");
                int v;
                do { asm volatile("ld.acquire.gpu.u32 %0, [%1];" : "=r"(v) : "l"(&g_gcnt[p])); }
                while (v < 64);
            }
            __syncthreads();
            query_phase(bx - 64, t, Wm, bm, sbuf, tid);
        }
        grid_sync();
        // update(t) + readvec(t-1) + dots + ||mem||^2 + ww sums (all blocks)
        update_phase((const float4*)g_rwbuf[p], bx, tid, sbuf, t);
        grid_sync();
    }
    if (bx < 64) softmax_uw_phase(g_rwbuf[SEQ & 1], bx, SEQ - 1, sbuf, tid);
    grid_sync();
    readvec_final(bx, NBLK, SEQ - 1, (const float4*)g_rwbuf[SEQ & 1], sbuf, tid);
}

__global__ __launch_bounds__(512) void k_probs(const float* __restrict__ Wf,
                                               const float* __restrict__ bf,
                                               float* __restrict__ out) {
    int g0 = blockIdx.x * 8;
    int tid = threadIdx.x;
    int row = tid >> 6, j = tid & 63;
    __shared__ float sin_[8][1024];
    for (int e = tid; e < 8192; e += 512)
        sin_[e >> 10][e & 1023] = g_outputs[(size_t)(g0 + (e >> 10)) * 1024 + (e & 1023)];
    __syncthreads();
    float acc = bf[j];
    #pragma unroll 8
    for (int k = 0; k < 1024; k++) acc += sin_[row][k] * Wf[k * 64 + j];
    __shared__ float lg[8][64];
    lg[row][j] = acc;
    __syncthreads();
    float mx = -FLT_MAX;
    #pragma unroll
    for (int q = 0; q < 64; q++) mx = fmaxf(mx, lg[row][q]);
    float sum = 0.f;
    #pragma unroll
    for (int q = 0; q < 64; q++) sum += expf(lg[row][q] - mx);
    out[(size_t)(g0 + row) * 64 + j] = expf(acc - mx) / sum;
}

// ---------------- vectorized copy of final states to output ---------------------
__global__ void k_final(float* __restrict__ out) {
    long tid = (long)blockIdx.x * blockDim.x + threadIdx.x;
    long stride = (long)gridDim.x * blockDim.x;
    const long P = (long)BSZ * SEQ * NOUT;
    const long MEMN = (long)BSZ * NN * MM;
    const long RWN = (long)BSZ * RHEAD * NN;
    float* pm = out + P;
    float* pr = pm + MEMN;
    float* pu = pr + RWN;
    const float4* rwfin4 = (const float4*)g_rwbuf[SEQ & 1];
    const float4* mem4 = (const float4*)g_mem;
    float4* pm4 = (float4*)pm;
    for (long i = tid; i < MEMN / 4; i += stride) pm4[i] = mem4[i];
    for (long i = tid; i < (long)BSZ*NN; i += stride) {
        long b = i >> 12, n = i & 4095;
        float4 v = rwfin4[i];
        float* rp = pr + ((b << 2) << 12) + n;
        rp[0]      = v.x;
        rp[NN]     = v.y;
        rp[2 * NN] = v.z;
        rp[3 * NN] = v.w;
    }
    const float4* uw4 = (const float4*)g_uw;
    float4* pu4 = (float4*)pu;
    for (long i = tid; i < (long)BSZ*NN/4; i += stride) pu4[i] = uw4[i];
}

extern "C" void kernel_launch(void* const* d_in, const int* in_sizes, int n_in,
                              void* d_out, int out_size) {
    const float* x     = (const float*)d_in[0];
    const float* y     = (const float*)d_in[1];
    const float* mem   = (const float*)d_in[2];
    const float* rw    = (const float*)d_in[3];
    const float* uw    = (const float*)d_in[4];
    const float* Wl    = (const float*)d_in[5];
    const float* bl    = (const float*)d_in[6];
    const float* Wm    = (const float*)d_in[7];
    const float* bm    = (const float*)d_in[8];
    const float* Wf    = (const float*)d_in[9];
    const float* bf    = (const float*)d_in[10];
    const float* alpha = (const float*)d_in[11];
    float* out = (float*)d_out;

    k_init<<<4096, 256>>>(mem, rw, uw, alpha);
    k_persist<<<NBLK, TPB>>>(x, y, Wl, bl, Wm, bm);
    k_probs<<<1024, 512>>>(Wf, bf, out);

    long total = 524288L + 33554432L + 1048576L + 262144L;
    if ((long)out_size >= total) {
        k_final<<<8192, 256>>>(out);
    }
}